// round 1
// baseline (speedup 1.0000x reference)
#include <cuda_runtime.h>

// Problem constants
#define NB 2
#define SS 2048
#define HH 4096
#define NQH 32
#define NKVH 8
#define DH 128
#define MTOT (NB*SS)          // 4096 tokens
#define QC (NQH*DH)           // 4096
#define KVC (NKVH*DH)         // 1024
#define QKVN (QC + 2*KVC)     // 6144

typedef unsigned long long u64;

// Scratch (device globals: allocation-free per harness rules)
__device__ float g_q[(size_t)MTOT*QC];     // RoPE'd Q
__device__ float g_k[(size_t)MTOT*KVC];    // RoPE'd K
__device__ float g_v[(size_t)MTOT*KVC];    // V
__device__ float g_attn[(size_t)MTOT*QC];  // attention output

// ---- packed f32x2 helpers (FFMA2 path on sm_103a) ----
__device__ __forceinline__ u64 pk2(float lo, float hi){
    u64 r; asm("mov.b64 %0,{%1,%2};" : "=l"(r) : "f"(lo), "f"(hi)); return r;
}
__device__ __forceinline__ void up2(u64 v, float& lo, float& hi){
    asm("mov.b64 {%0,%1},%2;" : "=f"(lo), "=f"(hi) : "l"(v));
}
__device__ __forceinline__ void fm2(u64& d, u64 a, u64 b){
    asm("fma.rn.f32x2 %0,%1,%2,%0;" : "+l"(d) : "l"(a), "l"(b));
}
__device__ __forceinline__ u64 ml2(u64 a, u64 b){
    u64 r; asm("mul.rn.f32x2 %0,%1,%2;" : "=l"(r) : "l"(a), "l"(b)); return r;
}

// =====================================================================
// GEMM: C[M,N] = A[M,K] * B[K,N], 128x128 block, 8x8 micro, f32x2 FMA.
// MODE 1: A=hidden, B=w_qkv, epilogue splits into g_q/g_k/g_v w/ RoPE.
// MODE 0: A=g_attn,  B=w_o,   epilogue writes C (=d_out).
// =====================================================================
#define BM 128
#define BN 128
#define BK 16
#define BPAD 4

template<int MODE>
__global__ __launch_bounds__(256, 2)
void gemm_kernel(const float* __restrict__ A_, const float* __restrict__ Bm,
                 float* __restrict__ C, const int* __restrict__ pos,
                 int M, int N, int K)
{
    __shared__ float As[BK][BM + BPAD];  // transposed A tile
    __shared__ float Bs[BK][BN + BPAD];

    const float* A = (MODE == 0) ? g_attn : A_;

    const int tid = threadIdx.x;
    const int tx = tid & 15, ty = tid >> 4;
    const int m0 = blockIdx.y * BM;
    const int n0 = blockIdx.x * BN;

    // global->shared load mapping
    const int ar = tid >> 2, ac4 = tid & 3;     // A: 64 rows x 4 quads per iter
    const int br = tid >> 5, bc4 = tid & 31;    // B: 8 k-rows x 32 quads per iter

    u64 acc[8][4];
    #pragma unroll
    for (int i = 0; i < 8; i++)
        #pragma unroll
        for (int j = 0; j < 4; j++) acc[i][j] = 0ull;

    const int nk = K / BK;
    float4 aR[2], bR[2];
    #pragma unroll
    for (int it = 0; it < 2; it++){
        aR[it] = *(const float4*)&A[(size_t)(m0 + ar + it*64)*K + ac4*4];
        bR[it] = *(const float4*)&Bm[(size_t)(br + it*8)*N + n0 + bc4*4];
    }

    for (int kt = 0; ; kt++){
        // stage prefetched tile into shared
        #pragma unroll
        for (int it = 0; it < 2; it++){
            As[ac4*4+0][ar+it*64] = aR[it].x;
            As[ac4*4+1][ar+it*64] = aR[it].y;
            As[ac4*4+2][ar+it*64] = aR[it].z;
            As[ac4*4+3][ar+it*64] = aR[it].w;
            *(float4*)&Bs[br+it*8][bc4*4] = bR[it];
        }
        __syncthreads();

        if (kt + 1 < nk){
            int k0 = (kt + 1) * BK;
            #pragma unroll
            for (int it = 0; it < 2; it++){
                aR[it] = *(const float4*)&A[(size_t)(m0 + ar + it*64)*K + k0 + ac4*4];
                bR[it] = *(const float4*)&Bm[(size_t)(k0 + br + it*8)*N + n0 + bc4*4];
            }
        }

        #pragma unroll
        for (int k = 0; k < BK; k++){
            u64 a2[8], b2[4];
            #pragma unroll
            for (int i = 0; i < 4; i++){
                float x = As[k][ty*4 + i];       a2[i]   = pk2(x, x);
                float y = As[k][64 + ty*4 + i];  a2[i+4] = pk2(y, y);
            }
            const u64* brow = (const u64*)&Bs[k][0];
            b2[0] = brow[tx*2];
            b2[1] = brow[tx*2 + 1];
            b2[2] = brow[32 + tx*2];
            b2[3] = brow[32 + tx*2 + 1];
            #pragma unroll
            for (int i = 0; i < 8; i++)
                #pragma unroll
                for (int j = 0; j < 4; j++) fm2(acc[i][j], a2[i], b2[j]);
        }

        if (kt + 1 >= nk) break;
        __syncthreads();
    }

    // epilogue
    #pragma unroll
    for (int i = 0; i < 8; i++){
        int m = m0 + ty*4 + (i & 3) + (i >> 2)*64;
        int p = 0;
        if (MODE == 1) p = pos[m];
        #pragma unroll
        for (int j = 0; j < 4; j++){
            int n = n0 + tx*4 + (j & 1)*2 + (j >> 1)*64;
            float x1, x2; up2(acc[i][j], x1, x2);
            if (MODE == 0){
                *(float2*)&C[(size_t)m*N + n] = make_float2(x1, x2);
            } else {
                // RoPE GPT-J: pairs are interleaved (even, odd) within head dim
                if (n < QC){
                    int d = n & (DH - 1);
                    float ang = (float)p * exp2f((float)(d >> 1) * (-13.287712379549449f / 64.f));
                    float sn, cs; sincosf(ang, &sn, &cs);
                    g_q[(size_t)m*QC + n]     = x1*cs - x2*sn;
                    g_q[(size_t)m*QC + n + 1] = x2*cs + x1*sn;
                } else if (n < QC + KVC){
                    int nk2 = n - QC;
                    int d = nk2 & (DH - 1);
                    float ang = (float)p * exp2f((float)(d >> 1) * (-13.287712379549449f / 64.f));
                    float sn, cs; sincosf(ang, &sn, &cs);
                    g_k[(size_t)m*KVC + nk2]     = x1*cs - x2*sn;
                    g_k[(size_t)m*KVC + nk2 + 1] = x2*cs + x1*sn;
                } else {
                    int nv = n - QC - KVC;
                    *(float2*)&g_v[(size_t)m*KVC + nv] = make_float2(x1, x2);
                }
            }
        }
    }
}

// =====================================================================
// Flash attention, fp32, causal, GQA (4 q-heads per kv head).
// Grid: (S/64, NQ, B). Block 256 = 16x16 threads.
// Each thread: 4 q-rows; S micro 4x4 (packed along D), O micro 4x8
// (packed along row pairs; cols strided tx + 16c → conflict-free LDS).
// =====================================================================
#define QK_PAD 130
#define QK_PAD64 65
#define V_STR 128
#define P_STR 65
#define ATTN_SMEM ((64*QK_PAD*2 + 64*V_STR + 64*P_STR)*4)

__global__ __launch_bounds__(256, 1)
void attn_kernel()
{
    extern __shared__ float smbuf[];
    float* Qs = smbuf;                  // 64 x 130
    float* Ks = Qs + 64*QK_PAD;         // 64 x 130
    float* Vs = Ks + 64*QK_PAD;         // 64 x 128
    float* Ps = Vs + 64*V_STR;          // 64 x 65

    const int tid = threadIdx.x;
    const int tx = tid & 15, ty = tid >> 4;
    const int qb = blockIdx.x, h = blockIdx.y, b = blockIdx.z;
    const int hk = h >> 2;              // GQA: NQ/NKV = 4
    const int q0 = qb * 64;
    const float scale = 0.08838834764831845f;  // 128^-0.5

    // load Q tile once (pre-scaled)
    #pragma unroll
    for (int it = 0; it < 8; it++){
        int idx = tid + it*256;
        int r = idx >> 5, c4 = idx & 31;
        float4 v = *(const float4*)&g_q[(size_t)(b*SS + q0 + r)*QC + h*DH + c4*4];
        *(float2*)&Qs[r*QK_PAD + c4*4]     = make_float2(v.x*scale, v.y*scale);
        *(float2*)&Qs[r*QK_PAD + c4*4 + 2] = make_float2(v.z*scale, v.w*scale);
    }

    u64 o2[2][8];
    #pragma unroll
    for (int pp = 0; pp < 2; pp++)
        #pragma unroll
        for (int c = 0; c < 8; c++) o2[pp][c] = 0ull;
    float mrow[4] = {-1e38f, -1e38f, -1e38f, -1e38f};
    float lrow[4] = {0.f, 0.f, 0.f, 0.f};

    for (int t = 0; t <= qb; t++){
        __syncthreads();   // prior PV reads done (and Q store visible on t=0)
        int k0 = t * 64;
        #pragma unroll
        for (int it = 0; it < 8; it++){
            int idx = tid + it*256;
            int r = idx >> 5, c4 = idx & 31;
            size_t gidx = (size_t)(b*SS + k0 + r)*KVC + hk*DH + c4*4;
            float4 kv4 = *(const float4*)&g_k[gidx];
            *(float2*)&Ks[r*QK_PAD + c4*4]     = make_float2(kv4.x, kv4.y);
            *(float2*)&Ks[r*QK_PAD + c4*4 + 2] = make_float2(kv4.z, kv4.w);
            float4 vv4 = *(const float4*)&g_v[gidx];
            *(float4*)&Vs[r*V_STR + c4*4] = vv4;
        }
        __syncthreads();

        // S = Q K^T  (f32x2 packed along D; horizontal add at end)
        u64 s2[4][4];
        #pragma unroll
        for (int i = 0; i < 4; i++)
            #pragma unroll
            for (int j = 0; j < 4; j++) s2[i][j] = 0ull;
        const u64* Q64 = (const u64*)Qs;
        const u64* K64 = (const u64*)Ks;
        #pragma unroll 8
        for (int d2 = 0; d2 < 64; d2++){
            u64 q2[4], k2[4];
            #pragma unroll
            for (int i = 0; i < 4; i++) q2[i] = Q64[(ty*4 + i)*QK_PAD64 + d2];
            #pragma unroll
            for (int j = 0; j < 4; j++) k2[j] = K64[(tx*4 + j)*QK_PAD64 + d2];
            #pragma unroll
            for (int i = 0; i < 4; i++)
                #pragma unroll
                for (int j = 0; j < 4; j++) fm2(s2[i][j], q2[i], k2[j]);
        }

        float sv[4][4];
        #pragma unroll
        for (int i = 0; i < 4; i++)
            #pragma unroll
            for (int j = 0; j < 4; j++){
                float lo, hi; up2(s2[i][j], lo, hi); sv[i][j] = lo + hi;
            }

        if (t == qb){  // causal mask only on the diagonal tile
            #pragma unroll
            for (int i = 0; i < 4; i++){
                int qg = q0 + ty*4 + i;
                #pragma unroll
                for (int j = 0; j < 4; j++){
                    int kg = k0 + tx*4 + j;
                    if (kg > qg) sv[i][j] = -1e30f;
                }
            }
        }

        // online softmax: rows owned by the 16 lanes sharing ty
        float al[4];
        #pragma unroll
        for (int i = 0; i < 4; i++){
            float rm = fmaxf(fmaxf(sv[i][0], sv[i][1]), fmaxf(sv[i][2], sv[i][3]));
            #pragma unroll
            for (int off = 8; off > 0; off >>= 1)
                rm = fmaxf(rm, __shfl_xor_sync(0xffffffffu, rm, off));
            float mn = fmaxf(mrow[i], rm);
            al[i] = __expf(mrow[i] - mn);
            mrow[i] = mn;
            float rs = 0.f;
            #pragma unroll
            for (int j = 0; j < 4; j++){
                float pv = __expf(sv[i][j] - mn); sv[i][j] = pv; rs += pv;
            }
            #pragma unroll
            for (int off = 8; off > 0; off >>= 1)
                rs += __shfl_xor_sync(0xffffffffu, rs, off);
            lrow[i] = lrow[i]*al[i] + rs;
            #pragma unroll
            for (int j = 0; j < 4; j++)
                Ps[(ty*4 + i)*P_STR + tx*4 + j] = sv[i][j];
        }

        // rescale O accumulators
        u64 al2[2] = { pk2(al[0], al[1]), pk2(al[2], al[3]) };
        #pragma unroll
        for (int c = 0; c < 8; c++){
            o2[0][c] = ml2(o2[0][c], al2[0]);
            o2[1][c] = ml2(o2[1][c], al2[1]);
        }

        __syncthreads();   // Ps visible to all

        // O += P V  (rows packed in pairs; V cols strided → conflict-free)
        #pragma unroll 4
        for (int kv = 0; kv < 64; kv++){
            float p0 = Ps[(ty*4 + 0)*P_STR + kv];
            float p1 = Ps[(ty*4 + 1)*P_STR + kv];
            float p2v = Ps[(ty*4 + 2)*P_STR + kv];
            float p3 = Ps[(ty*4 + 3)*P_STR + kv];
            u64 pa = pk2(p0, p1), pb = pk2(p2v, p3);
            #pragma unroll
            for (int c = 0; c < 8; c++){
                float v = Vs[kv*V_STR + tx + 16*c];
                u64 v2 = pk2(v, v);
                fm2(o2[0][c], pa, v2);
                fm2(o2[1][c], pb, v2);
            }
        }
    }

    float inv0 = 1.f/lrow[0], inv1 = 1.f/lrow[1];
    float inv2 = 1.f/lrow[2], inv3 = 1.f/lrow[3];
    #pragma unroll
    for (int c = 0; c < 8; c++){
        float a, bb; up2(o2[0][c], a, bb);
        float d, e;  up2(o2[1][c], d, e);
        int col = h*DH + tx + 16*c;
        size_t base = (size_t)(b*SS + q0 + ty*4)*QC + col;
        g_attn[base]        = a  * inv0;
        g_attn[base + QC]   = bb * inv1;
        g_attn[base + 2*QC] = d  * inv2;
        g_attn[base + 3*QC] = e  * inv3;
    }
}

// =====================================================================
extern "C" void kernel_launch(void* const* d_in, const int* in_sizes, int n_in,
                              void* d_out, int out_size)
{
    const float* hidden = (const float*)d_in[0];
    const float* wqkv   = (const float*)d_in[1];
    const float* wo     = (const float*)d_in[2];
    const int*   pos    = (const int*)d_in[3];
    float* out = (float*)d_out;

    cudaFuncSetAttribute(attn_kernel,
                         cudaFuncAttributeMaxDynamicSharedMemorySize, ATTN_SMEM);

    // 1) QKV projection + RoPE split
    gemm_kernel<1><<<dim3(QKVN/BN, MTOT/BM), 256>>>(
        hidden, wqkv, (float*)nullptr, pos, MTOT, QKVN, HH);

    // 2) causal GQA flash attention
    attn_kernel<<<dim3(SS/64, NQH, NB), 256, ATTN_SMEM>>>();

    // 3) output projection
    gemm_kernel<0><<<dim3(HH/BN, MTOT/BM), 256>>>(
        (const float*)nullptr, wo, out, pos, MTOT, HH, QC);
}

// round 3
// speedup vs baseline: 1.4085x; 1.4085x over previous
#include <cuda_runtime.h>
#include <cuda_bf16.h>

// Problem constants
#define NB 2
#define SS 2048
#define HH 4096
#define NQH 32
#define NKVH 8
#define DH 128
#define MTOT (NB*SS)          // 4096 tokens
#define QC (NQH*DH)           // 4096
#define KVC (NKVH*DH)         // 1024
#define QKVN (QC + 2*KVC)     // 6144

typedef unsigned long long u64;
typedef unsigned int u32;

// ---------------- scratch (device globals; no allocation) ----------------
__device__ float g_q[(size_t)MTOT*QC];
__device__ float g_k[(size_t)MTOT*KVC];
__device__ float g_v[(size_t)MTOT*KVC];
__device__ float g_attn[(size_t)MTOT*QC];

// bf16 split operands
__device__ __nv_bfloat16 g_hA_hi[(size_t)MTOT*HH];
__device__ __nv_bfloat16 g_hA_lo[(size_t)MTOT*HH];
__device__ __nv_bfloat16 g_wqkvT_hi[(size_t)QKVN*HH];
__device__ __nv_bfloat16 g_wqkvT_lo[(size_t)QKVN*HH];
__device__ __nv_bfloat16 g_aA_hi[(size_t)MTOT*QC];
__device__ __nv_bfloat16 g_aA_lo[(size_t)MTOT*QC];
__device__ __nv_bfloat16 g_woT_hi[(size_t)HH*QC];
__device__ __nv_bfloat16 g_woT_lo[(size_t)HH*QC];

// ---------------- PTX helpers ----------------
__device__ __forceinline__ u32 smem_u32(const void* p){
    u32 a; asm("{ .reg .u64 t; cvta.to.shared.u64 t, %1; cvt.u32.u64 %0, t; }" : "=r"(a) : "l"(p));
    return a;
}
__device__ __forceinline__ void cpa16(u32 s, const void* g){
    asm volatile("cp.async.cg.shared.global [%0], [%1], 16;" :: "r"(s), "l"(g));
}
__device__ __forceinline__ void cp_commit(){ asm volatile("cp.async.commit_group;"); }
template<int N> __device__ __forceinline__ void cp_wait(){
    asm volatile("cp.async.wait_group %0;" :: "n"(N));
}
__device__ __forceinline__ void ldm_x4(u32 addr, u32& r0, u32& r1, u32& r2, u32& r3){
    asm volatile("ldmatrix.sync.aligned.m8n8.x4.shared.b16 {%0,%1,%2,%3}, [%4];"
                 : "=r"(r0), "=r"(r1), "=r"(r2), "=r"(r3) : "r"(addr));
}
__device__ __forceinline__ void mma16816(float* c, const u32* a, const u32* b){
    asm volatile("mma.sync.aligned.m16n8k16.row.col.f32.bf16.bf16.f32 "
                 "{%0,%1,%2,%3}, {%4,%5,%6,%7}, {%8,%9}, {%0,%1,%2,%3};"
                 : "+f"(c[0]), "+f"(c[1]), "+f"(c[2]), "+f"(c[3])
                 : "r"(a[0]), "r"(a[1]), "r"(a[2]), "r"(a[3]), "r"(b[0]), "r"(b[1]));
}

// packed f32x2 helpers (attention kernel)
__device__ __forceinline__ u64 pk2(float lo, float hi){
    u64 r; asm("mov.b64 %0,{%1,%2};" : "=l"(r) : "f"(lo), "f"(hi)); return r;
}
__device__ __forceinline__ void up2(u64 v, float& lo, float& hi){
    asm("mov.b64 {%0,%1},%2;" : "=f"(lo), "=f"(hi) : "l"(v));
}
__device__ __forceinline__ void fm2(u64& d, u64 a, u64 b){
    asm("fma.rn.f32x2 %0,%1,%2,%0;" : "+l"(d) : "l"(a), "l"(b));
}
__device__ __forceinline__ u64 ml2(u64 a, u64 b){
    u64 r; asm("mul.rn.f32x2 %0,%1,%2;" : "=l"(r) : "l"(a), "l"(b)); return r;
}

// =====================================================================
// Split-convert kernels (fp32 -> bf16 hi + bf16 lo residual)
// =====================================================================
__global__ void conv_split4(const float4* __restrict__ src,
                            ushort4* __restrict__ hi, ushort4* __restrict__ lo, int n4)
{
    int i = blockIdx.x * blockDim.x + threadIdx.x;
    if (i >= n4) return;
    float4 x = src[i];
    __nv_bfloat16 h0 = __float2bfloat16(x.x), h1 = __float2bfloat16(x.y);
    __nv_bfloat16 h2 = __float2bfloat16(x.z), h3 = __float2bfloat16(x.w);
    hi[i] = make_ushort4(__bfloat16_as_ushort(h0), __bfloat16_as_ushort(h1),
                         __bfloat16_as_ushort(h2), __bfloat16_as_ushort(h3));
    __nv_bfloat16 l0 = __float2bfloat16(x.x - __bfloat162float(h0));
    __nv_bfloat16 l1 = __float2bfloat16(x.y - __bfloat162float(h1));
    __nv_bfloat16 l2 = __float2bfloat16(x.z - __bfloat162float(h2));
    __nv_bfloat16 l3 = __float2bfloat16(x.w - __bfloat162float(h3));
    lo[i] = make_ushort4(__bfloat16_as_ushort(l0), __bfloat16_as_ushort(l1),
                         __bfloat16_as_ushort(l2), __bfloat16_as_ushort(l3));
}

// transpose + split: src[R][C] fp32 -> dst[C][R] bf16 hi/lo
__global__ void conv_splitT(const float* __restrict__ src,
                            __nv_bfloat16* __restrict__ hiT, __nv_bfloat16* __restrict__ loT,
                            int R, int Cc)
{
    __shared__ float t[64][33];
    int r0 = blockIdx.y * 64, c0 = blockIdx.x * 32;
    int tx = threadIdx.x, ty = threadIdx.y;  // (32,8)
    #pragma unroll
    for (int i = 0; i < 8; i++){
        int r = ty + i*8;
        t[r][tx] = src[(size_t)(r0 + r) * Cc + c0 + tx];
    }
    __syncthreads();
    #pragma unroll
    for (int i = 0; i < 4; i++){
        int cc = ty + i*8;
        float x0 = t[tx*2][cc], x1 = t[tx*2+1][cc];
        __nv_bfloat16 h0 = __float2bfloat16(x0), h1 = __float2bfloat16(x1);
        __nv_bfloat162 hv; hv.x = h0; hv.y = h1;
        __nv_bfloat162 lv;
        lv.x = __float2bfloat16(x0 - __bfloat162float(h0));
        lv.y = __float2bfloat16(x1 - __bfloat162float(h1));
        size_t o = (size_t)(c0 + cc) * R + r0 + tx*2;
        *(__nv_bfloat162*)(hiT + o) = hv;
        *(__nv_bfloat162*)(loT + o) = lv;
    }
}

// =====================================================================
// HMMA bf16x3 GEMM: C[M,N] = A[M,K] * B[N,K]^T.
// 128x128 CTA tile, BK=32, 8 warps (32x64 each), cp.async double buffer.
// MODE 1: epilogue splits into g_q/g_k/g_v with RoPE. MODE 0: writes C.
// =====================================================================
#define GBK 32
#define ASTRB 80                       // bytes per 32-elem row (16B pad)
#define TILEB (128*ASTRB)              // 10240 B per operand tile
#define STAGEB (4*TILEB)               // Ahi,Alo,Bhi,Blo
#define GSM (2*STAGEB)                 // 81920 B

template<int MODE>
__global__ __launch_bounds__(256, 1)
void mma_gemm(const __nv_bfloat16* __restrict__ Ahi, const __nv_bfloat16* __restrict__ Alo,
              const __nv_bfloat16* __restrict__ Bhi, const __nv_bfloat16* __restrict__ Blo,
              float* __restrict__ C, const int* __restrict__ pos, int N, int K)
{
    extern __shared__ __align__(128) char sm[];
    const u32 sbuf = smem_u32(sm);
    const int tid = threadIdx.x, wid = tid >> 5, lid = tid & 31;
    const int wm = wid & 3, wn = wid >> 2;           // warp grid 4(M) x 2(N)
    const int m0 = blockIdx.x * 128;
    const int n0 = blockIdx.y * 128;
    const int nk = K / GBK;

    float acc[2][8][4];
    #pragma unroll
    for (int t = 0; t < 2; t++)
        #pragma unroll
        for (int j = 0; j < 8; j++)
            #pragma unroll
            for (int q = 0; q < 4; q++) acc[t][j][q] = 0.f;

    // tile loader: 512 x 16B chunks, 2 per thread
    auto ldtile = [&](const __nv_bfloat16* g, int row0, int kc, u32 sb){
        #pragma unroll
        for (int i = 0; i < 2; i++){
            int c = tid + i*256;
            int r = c >> 2, kg = c & 3;
            cpa16(sb + r*ASTRB + kg*16, g + (size_t)(row0 + r)*K + kc + kg*8);
        }
    };
    auto ldstage = [&](int kc, int s){
        u32 sb = sbuf + s*STAGEB;
        ldtile(Ahi, m0, kc, sb);
        ldtile(Alo, m0, kc, sb + TILEB);
        ldtile(Bhi, n0, kc, sb + 2*TILEB);
        ldtile(Blo, n0, kc, sb + 3*TILEB);
        cp_commit();
    };

    // ldmatrix lane addresses (within a stage buffer)
    const u32 a_row = (u32)(wm*32 + (lid & 15));
    const u32 a_kb  = (u32)((lid >> 4) * 16);            // bytes
    const int bg = lid >> 3, br = lid & 7;
    const u32 b_base_n = (u32)(wn*64 + ((bg >> 1) << 3) + br);
    const u32 b_kb = (u32)((bg & 1) * 16);               // bytes

    ldstage(0, 0);

    for (int kt = 0; kt < nk; kt++){
        if (kt + 1 < nk){ ldstage((kt + 1)*GBK, (kt + 1) & 1); cp_wait<1>(); }
        else cp_wait<0>();
        __syncthreads();

        u32 ab = sbuf + (kt & 1)*STAGEB;
        #pragma unroll
        for (int k16 = 0; k16 < 2; k16++){
            u32 kb = (u32)(k16 * 32);
            u32 ah[2][4], al[2][4], bh[8][2], bl[8][2];
            #pragma unroll
            for (int t = 0; t < 2; t++){
                u32 ad = ab + (a_row + t*16)*ASTRB + kb + a_kb;
                ldm_x4(ad, ah[t][0], ah[t][1], ah[t][2], ah[t][3]);
                ldm_x4(ad + TILEB, al[t][0], al[t][1], al[t][2], al[t][3]);
            }
            #pragma unroll
            for (int p = 0; p < 4; p++){
                u32 bd = ab + 2*TILEB + (b_base_n + p*16)*ASTRB + kb + b_kb;
                ldm_x4(bd, bh[2*p][0], bh[2*p][1], bh[2*p+1][0], bh[2*p+1][1]);
                ldm_x4(bd + TILEB, bl[2*p][0], bl[2*p][1], bl[2*p+1][0], bl[2*p+1][1]);
            }
            #pragma unroll
            for (int t = 0; t < 2; t++)
                #pragma unroll
                for (int j = 0; j < 8; j++){
                    mma16816(acc[t][j], ah[t], bh[j]);
                    mma16816(acc[t][j], ah[t], bl[j]);
                    mma16816(acc[t][j], al[t], bh[j]);
                }
        }
        __syncthreads();
    }

    // ---------------- epilogue ----------------
    const int mrow0 = m0 + wm*32 + (lid >> 2);
    const int colw = wn*64 + 2*(lid & 3);               // col within 128-tile
    if (MODE == 0){
        #pragma unroll
        for (int t = 0; t < 2; t++)
            #pragma unroll
            for (int j = 0; j < 8; j++){
                int m = mrow0 + t*16;
                int nc = n0 + colw + j*8;
                *(float2*)&C[(size_t)m*N + nc]     = make_float2(acc[t][j][0], acc[t][j][1]);
                *(float2*)&C[(size_t)(m+8)*N + nc] = make_float2(acc[t][j][2], acc[t][j][3]);
            }
    } else {
        const int head = blockIdx.y;                    // BN == DH
        if (head < NQH + NKVH){
            #pragma unroll
            for (int t = 0; t < 2; t++){
                int m = mrow0 + t*16;
                int p0 = pos[m], p1 = pos[m + 8];
                float* dst = (head < NQH) ? (g_q + (size_t)0 + head*DH)
                                          : (g_k + (size_t)0 + (head - NQH)*DH);
                size_t rs = (head < NQH) ? (size_t)QC : (size_t)KVC;
                #pragma unroll
                for (int j = 0; j < 8; j++){
                    int d = colw + j*8;
                    float invf = exp2f((float)(d >> 1) * (-13.287712379549449f / 64.f));
                    float s0, c0s, s1, c1s;
                    sincosf((float)p0 * invf, &s0, &c0s);
                    sincosf((float)p1 * invf, &s1, &c1s);
                    float x1 = acc[t][j][0], x2 = acc[t][j][1];
                    *(float2*)&dst[(size_t)m*rs + d] =
                        make_float2(x1*c0s - x2*s0, x2*c0s + x1*s0);
                    float y1 = acc[t][j][2], y2 = acc[t][j][3];
                    *(float2*)&dst[(size_t)(m+8)*rs + d] =
                        make_float2(y1*c1s - y2*s1, y2*c1s + y1*s1);
                }
            }
        } else {
            const int hv = head - NQH - NKVH;
            #pragma unroll
            for (int t = 0; t < 2; t++)
                #pragma unroll
                for (int j = 0; j < 8; j++){
                    int m = mrow0 + t*16;
                    int d = colw + j*8;
                    *(float2*)&g_v[(size_t)m*KVC + hv*DH + d] =
                        make_float2(acc[t][j][0], acc[t][j][1]);
                    *(float2*)&g_v[(size_t)(m+8)*KVC + hv*DH + d] =
                        make_float2(acc[t][j][2], acc[t][j][3]);
                }
        }
    }
}

// =====================================================================
// Flash attention, fp32, causal, GQA (unchanged, known-good)
// =====================================================================
#define QK_PAD 130
#define QK_PAD64 65
#define V_STR 128
#define P_STR 65
#define ATTN_SMEM ((64*QK_PAD*2 + 64*V_STR + 64*P_STR)*4)

__global__ __launch_bounds__(256, 1)
void attn_kernel()
{
    extern __shared__ float smbuf[];
    float* Qs = smbuf;
    float* Ks = Qs + 64*QK_PAD;
    float* Vs = Ks + 64*QK_PAD;
    float* Ps = Vs + 64*V_STR;

    const int tid = threadIdx.x;
    const int tx = tid & 15, ty = tid >> 4;
    const int qb = blockIdx.x, h = blockIdx.y, b = blockIdx.z;
    const int hk = h >> 2;
    const int q0 = qb * 64;
    const float scale = 0.08838834764831845f;

    #pragma unroll
    for (int it = 0; it < 8; it++){
        int idx = tid + it*256;
        int r = idx >> 5, c4 = idx & 31;
        float4 v = *(const float4*)&g_q[(size_t)(b*SS + q0 + r)*QC + h*DH + c4*4];
        *(float2*)&Qs[r*QK_PAD + c4*4]     = make_float2(v.x*scale, v.y*scale);
        *(float2*)&Qs[r*QK_PAD + c4*4 + 2] = make_float2(v.z*scale, v.w*scale);
    }

    u64 o2[2][8];
    #pragma unroll
    for (int pp = 0; pp < 2; pp++)
        #pragma unroll
        for (int c = 0; c < 8; c++) o2[pp][c] = 0ull;
    float mrow[4] = {-1e38f, -1e38f, -1e38f, -1e38f};
    float lrow[4] = {0.f, 0.f, 0.f, 0.f};

    for (int t = 0; t <= qb; t++){
        __syncthreads();
        int k0 = t * 64;
        #pragma unroll
        for (int it = 0; it < 8; it++){
            int idx = tid + it*256;
            int r = idx >> 5, c4 = idx & 31;
            size_t gidx = (size_t)(b*SS + k0 + r)*KVC + hk*DH + c4*4;
            float4 kv4 = *(const float4*)&g_k[gidx];
            *(float2*)&Ks[r*QK_PAD + c4*4]     = make_float2(kv4.x, kv4.y);
            *(float2*)&Ks[r*QK_PAD + c4*4 + 2] = make_float2(kv4.z, kv4.w);
            float4 vv4 = *(const float4*)&g_v[gidx];
            *(float4*)&Vs[r*V_STR + c4*4] = vv4;
        }
        __syncthreads();

        u64 s2[4][4];
        #pragma unroll
        for (int i = 0; i < 4; i++)
            #pragma unroll
            for (int j = 0; j < 4; j++) s2[i][j] = 0ull;
        const u64* Q64 = (const u64*)Qs;
        const u64* K64 = (const u64*)Ks;
        #pragma unroll 8
        for (int d2 = 0; d2 < 64; d2++){
            u64 q2[4], k2[4];
            #pragma unroll
            for (int i = 0; i < 4; i++) q2[i] = Q64[(ty*4 + i)*QK_PAD64 + d2];
            #pragma unroll
            for (int j = 0; j < 4; j++) k2[j] = K64[(tx*4 + j)*QK_PAD64 + d2];
            #pragma unroll
            for (int i = 0; i < 4; i++)
                #pragma unroll
                for (int j = 0; j < 4; j++) fm2(s2[i][j], q2[i], k2[j]);
        }

        float sv[4][4];
        #pragma unroll
        for (int i = 0; i < 4; i++)
            #pragma unroll
            for (int j = 0; j < 4; j++){
                float lo, hi; up2(s2[i][j], lo, hi); sv[i][j] = lo + hi;
            }

        if (t == qb){
            #pragma unroll
            for (int i = 0; i < 4; i++){
                int qg = q0 + ty*4 + i;
                #pragma unroll
                for (int j = 0; j < 4; j++){
                    int kg = k0 + tx*4 + j;
                    if (kg > qg) sv[i][j] = -1e30f;
                }
            }
        }

        float al[4];
        #pragma unroll
        for (int i = 0; i < 4; i++){
            float rm = fmaxf(fmaxf(sv[i][0], sv[i][1]), fmaxf(sv[i][2], sv[i][3]));
            #pragma unroll
            for (int off = 8; off > 0; off >>= 1)
                rm = fmaxf(rm, __shfl_xor_sync(0xffffffffu, rm, off));
            float mn = fmaxf(mrow[i], rm);
            al[i] = __expf(mrow[i] - mn);
            mrow[i] = mn;
            float rs = 0.f;
            #pragma unroll
            for (int j = 0; j < 4; j++){
                float pv = __expf(sv[i][j] - mn); sv[i][j] = pv; rs += pv;
            }
            #pragma unroll
            for (int off = 8; off > 0; off >>= 1)
                rs += __shfl_xor_sync(0xffffffffu, rs, off);
            lrow[i] = lrow[i]*al[i] + rs;
            #pragma unroll
            for (int j = 0; j < 4; j++)
                Ps[(ty*4 + i)*P_STR + tx*4 + j] = sv[i][j];
        }

        u64 al2[2] = { pk2(al[0], al[1]), pk2(al[2], al[3]) };
        #pragma unroll
        for (int c = 0; c < 8; c++){
            o2[0][c] = ml2(o2[0][c], al2[0]);
            o2[1][c] = ml2(o2[1][c], al2[1]);
        }

        __syncthreads();

        #pragma unroll 4
        for (int kv = 0; kv < 64; kv++){
            float p0 = Ps[(ty*4 + 0)*P_STR + kv];
            float p1 = Ps[(ty*4 + 1)*P_STR + kv];
            float p2v = Ps[(ty*4 + 2)*P_STR + kv];
            float p3 = Ps[(ty*4 + 3)*P_STR + kv];
            u64 pa = pk2(p0, p1), pb = pk2(p2v, p3);
            #pragma unroll
            for (int c = 0; c < 8; c++){
                float v = Vs[kv*V_STR + tx + 16*c];
                u64 v2 = pk2(v, v);
                fm2(o2[0][c], pa, v2);
                fm2(o2[1][c], pb, v2);
            }
        }
    }

    float inv0 = 1.f/lrow[0], inv1 = 1.f/lrow[1];
    float inv2 = 1.f/lrow[2], inv3 = 1.f/lrow[3];
    #pragma unroll
    for (int c = 0; c < 8; c++){
        float a, bb; up2(o2[0][c], a, bb);
        float d, e;  up2(o2[1][c], d, e);
        int col = h*DH + tx + 16*c;
        size_t base = (size_t)(b*SS + q0 + ty*4)*QC + col;
        g_attn[base]        = a  * inv0;
        g_attn[base + QC]   = bb * inv1;
        g_attn[base + 2*QC] = d  * inv2;
        g_attn[base + 3*QC] = e  * inv3;
    }
}

// =====================================================================
extern "C" void kernel_launch(void* const* d_in, const int* in_sizes, int n_in,
                              void* d_out, int out_size)
{
    const float* hidden = (const float*)d_in[0];
    const float* wqkv   = (const float*)d_in[1];
    const float* wo     = (const float*)d_in[2];
    const int*   pos    = (const int*)d_in[3];
    float* out = (float*)d_out;

    void *p_hA_hi, *p_hA_lo, *p_wqkvT_hi, *p_wqkvT_lo;
    void *p_aA_hi, *p_aA_lo, *p_woT_hi, *p_woT_lo, *p_attn;
    cudaGetSymbolAddress(&p_hA_hi, g_hA_hi);
    cudaGetSymbolAddress(&p_hA_lo, g_hA_lo);
    cudaGetSymbolAddress(&p_wqkvT_hi, g_wqkvT_hi);
    cudaGetSymbolAddress(&p_wqkvT_lo, g_wqkvT_lo);
    cudaGetSymbolAddress(&p_aA_hi, g_aA_hi);
    cudaGetSymbolAddress(&p_aA_lo, g_aA_lo);
    cudaGetSymbolAddress(&p_woT_hi, g_woT_hi);
    cudaGetSymbolAddress(&p_woT_lo, g_woT_lo);
    cudaGetSymbolAddress(&p_attn, g_attn);

    cudaFuncSetAttribute(mma_gemm<1>, cudaFuncAttributeMaxDynamicSharedMemorySize, GSM);
    cudaFuncSetAttribute(mma_gemm<0>, cudaFuncAttributeMaxDynamicSharedMemorySize, GSM);
    cudaFuncSetAttribute(attn_kernel, cudaFuncAttributeMaxDynamicSharedMemorySize, ATTN_SMEM);

    // 1) split hidden into bf16 hi/lo
    {
        int n4 = (int)((size_t)MTOT * HH / 4);
        conv_split4<<<(n4 + 255)/256, 256>>>((const float4*)hidden,
                                             (ushort4*)p_hA_hi, (ushort4*)p_hA_lo, n4);
    }
    // 2) transpose+split weights -> [N][K] bf16 hi/lo
    conv_splitT<<<dim3(QKVN/32, HH/64), dim3(32, 8)>>>(
        wqkv, (__nv_bfloat16*)p_wqkvT_hi, (__nv_bfloat16*)p_wqkvT_lo, HH, QKVN);
    conv_splitT<<<dim3(HH/32, QC/64), dim3(32, 8)>>>(
        wo, (__nv_bfloat16*)p_woT_hi, (__nv_bfloat16*)p_woT_lo, QC, HH);

    // 3) QKV projection (HMMA bf16x3) + fused RoPE/split epilogue
    mma_gemm<1><<<dim3(MTOT/128, QKVN/128), 256, GSM>>>(
        (const __nv_bfloat16*)p_hA_hi, (const __nv_bfloat16*)p_hA_lo,
        (const __nv_bfloat16*)p_wqkvT_hi, (const __nv_bfloat16*)p_wqkvT_lo,
        nullptr, pos, QKVN, HH);

    // 4) causal GQA flash attention (fp32)
    attn_kernel<<<dim3(SS/64, NQH, NB), 256, ATTN_SMEM>>>();

    // 5) split attention output
    {
        int n4 = (int)((size_t)MTOT * QC / 4);
        conv_split4<<<(n4 + 255)/256, 256>>>((const float4*)p_attn,
                                             (ushort4*)p_aA_hi, (ushort4*)p_aA_lo, n4);
    }
    // 6) output projection (HMMA bf16x3)
    mma_gemm<0><<<dim3(MTOT/128, HH/128), 256, GSM>>>(
        (const __nv_bfloat16*)p_aA_hi, (const __nv_bfloat16*)p_aA_lo,
        (const __nv_bfloat16*)p_woT_hi, (const __nv_bfloat16*)p_woT_lo,
        out, nullptr, HH, QC);
}

// round 4
// speedup vs baseline: 2.6292x; 1.8666x over previous
#include <cuda_runtime.h>
#include <cuda_bf16.h>

// Problem constants
#define NB 2
#define SS 2048
#define HH 4096
#define NQH 32
#define NKVH 8
#define DH 128
#define MTOT (NB*SS)          // 4096 tokens
#define QC (NQH*DH)           // 4096
#define KVC (NKVH*DH)         // 1024
#define QKVN (QC + 2*KVC)     // 6144

typedef unsigned long long u64;
typedef unsigned int u32;
typedef unsigned short u16;

// ---------------- scratch (device globals; no allocation) ----------------
// bf16 hi/lo split operands
__device__ __nv_bfloat16 g_hA_hi[(size_t)MTOT*HH];
__device__ __nv_bfloat16 g_hA_lo[(size_t)MTOT*HH];
__device__ __nv_bfloat16 g_wqkvT_hi[(size_t)QKVN*HH];
__device__ __nv_bfloat16 g_wqkvT_lo[(size_t)QKVN*HH];
__device__ __nv_bfloat16 g_aA_hi[(size_t)MTOT*QC];
__device__ __nv_bfloat16 g_aA_lo[(size_t)MTOT*QC];
__device__ __nv_bfloat16 g_woT_hi[(size_t)HH*QC];
__device__ __nv_bfloat16 g_woT_lo[(size_t)HH*QC];
// Q/K/V in bf16 hi/lo (Q pre-scaled + RoPE'd, K RoPE'd)
__device__ __nv_bfloat16 g_qh[(size_t)MTOT*QC];
__device__ __nv_bfloat16 g_ql[(size_t)MTOT*QC];
__device__ __nv_bfloat16 g_kh[(size_t)MTOT*KVC];
__device__ __nv_bfloat16 g_kl[(size_t)MTOT*KVC];
__device__ __nv_bfloat16 g_vh[(size_t)MTOT*KVC];
__device__ __nv_bfloat16 g_vl[(size_t)MTOT*KVC];

// ---------------- PTX helpers ----------------
__device__ __forceinline__ u32 smem_u32(const void* p){
    u32 a; asm("{ .reg .u64 t; cvta.to.shared.u64 t, %1; cvt.u32.u64 %0, t; }" : "=r"(a) : "l"(p));
    return a;
}
__device__ __forceinline__ void cpa16(u32 s, const void* g){
    asm volatile("cp.async.cg.shared.global [%0], [%1], 16;" :: "r"(s), "l"(g));
}
__device__ __forceinline__ void cp_commit(){ asm volatile("cp.async.commit_group;"); }
template<int N> __device__ __forceinline__ void cp_wait(){
    asm volatile("cp.async.wait_group %0;" :: "n"(N));
}
__device__ __forceinline__ void ldm_x4(u32 addr, u32& r0, u32& r1, u32& r2, u32& r3){
    asm volatile("ldmatrix.sync.aligned.m8n8.x4.shared.b16 {%0,%1,%2,%3}, [%4];"
                 : "=r"(r0), "=r"(r1), "=r"(r2), "=r"(r3) : "r"(addr));
}
__device__ __forceinline__ void ldm_x4t(u32 addr, u32& r0, u32& r1, u32& r2, u32& r3){
    asm volatile("ldmatrix.sync.aligned.m8n8.x4.trans.shared.b16 {%0,%1,%2,%3}, [%4];"
                 : "=r"(r0), "=r"(r1), "=r"(r2), "=r"(r3) : "r"(addr));
}
__device__ __forceinline__ void mma16816(float* c, const u32* a, u32 b0, u32 b1){
    asm volatile("mma.sync.aligned.m16n8k16.row.col.f32.bf16.bf16.f32 "
                 "{%0,%1,%2,%3}, {%4,%5,%6,%7}, {%8,%9}, {%0,%1,%2,%3};"
                 : "+f"(c[0]), "+f"(c[1]), "+f"(c[2]), "+f"(c[3])
                 : "r"(a[0]), "r"(a[1]), "r"(a[2]), "r"(a[3]), "r"(b0), "r"(b1));
}
// split two fp32 into packed bf16 hi-pair + lo-pair (low half = first arg)
__device__ __forceinline__ void split2(float x0, float x1, u32& hi, u32& lo){
    __nv_bfloat16 h0 = __float2bfloat16(x0), h1 = __float2bfloat16(x1);
    hi = (u32)__bfloat16_as_ushort(h0) | ((u32)__bfloat16_as_ushort(h1) << 16);
    __nv_bfloat16 l0 = __float2bfloat16(x0 - __bfloat162float(h0));
    __nv_bfloat16 l1 = __float2bfloat16(x1 - __bfloat162float(h1));
    lo = (u32)__bfloat16_as_ushort(l0) | ((u32)__bfloat16_as_ushort(l1) << 16);
}

// =====================================================================
// Split-convert kernels
// =====================================================================
__global__ void conv_split4(const float4* __restrict__ src,
                            ushort4* __restrict__ hi, ushort4* __restrict__ lo, int n4)
{
    int i = blockIdx.x * blockDim.x + threadIdx.x;
    if (i >= n4) return;
    float4 x = src[i];
    __nv_bfloat16 h0 = __float2bfloat16(x.x), h1 = __float2bfloat16(x.y);
    __nv_bfloat16 h2 = __float2bfloat16(x.z), h3 = __float2bfloat16(x.w);
    hi[i] = make_ushort4(__bfloat16_as_ushort(h0), __bfloat16_as_ushort(h1),
                         __bfloat16_as_ushort(h2), __bfloat16_as_ushort(h3));
    __nv_bfloat16 l0 = __float2bfloat16(x.x - __bfloat162float(h0));
    __nv_bfloat16 l1 = __float2bfloat16(x.y - __bfloat162float(h1));
    __nv_bfloat16 l2 = __float2bfloat16(x.z - __bfloat162float(h2));
    __nv_bfloat16 l3 = __float2bfloat16(x.w - __bfloat162float(h3));
    lo[i] = make_ushort4(__bfloat16_as_ushort(l0), __bfloat16_as_ushort(l1),
                         __bfloat16_as_ushort(l2), __bfloat16_as_ushort(l3));
}

__global__ void conv_splitT(const float* __restrict__ src,
                            __nv_bfloat16* __restrict__ hiT, __nv_bfloat16* __restrict__ loT,
                            int R, int Cc)
{
    __shared__ float t[64][33];
    int r0 = blockIdx.y * 64, c0 = blockIdx.x * 32;
    int tx = threadIdx.x, ty = threadIdx.y;  // (32,8)
    #pragma unroll
    for (int i = 0; i < 8; i++){
        int r = ty + i*8;
        t[r][tx] = src[(size_t)(r0 + r) * Cc + c0 + tx];
    }
    __syncthreads();
    #pragma unroll
    for (int i = 0; i < 4; i++){
        int cc = ty + i*8;
        float x0 = t[tx*2][cc], x1 = t[tx*2+1][cc];
        __nv_bfloat16 h0 = __float2bfloat16(x0), h1 = __float2bfloat16(x1);
        __nv_bfloat162 hv; hv.x = h0; hv.y = h1;
        __nv_bfloat162 lv;
        lv.x = __float2bfloat16(x0 - __bfloat162float(h0));
        lv.y = __float2bfloat16(x1 - __bfloat162float(h1));
        size_t o = (size_t)(c0 + cc) * R + r0 + tx*2;
        *(__nv_bfloat162*)(hiT + o) = hv;
        *(__nv_bfloat162*)(loT + o) = lv;
    }
}

// =====================================================================
// HMMA bf16x3 GEMM: C[M,N] = A[M,K] * B[N,K]^T.
// 128x128 CTA tile, BK=32, 8 warps (32x64 each), cp.async double buffer.
// 2 CTAs/SM. MODE 1: epilogue -> Q/K/V bf16 hi/lo w/ RoPE. MODE 0: C fp32.
// =====================================================================
#define GBK 32
#define ASTRB 80
#define TILEB (128*ASTRB)
#define STAGEB (4*TILEB)
#define GSM (2*STAGEB)                 // 81920 B

template<int MODE>
__global__ __launch_bounds__(256, 2)
void mma_gemm(const __nv_bfloat16* __restrict__ Ahi, const __nv_bfloat16* __restrict__ Alo,
              const __nv_bfloat16* __restrict__ Bhi, const __nv_bfloat16* __restrict__ Blo,
              float* __restrict__ C, const int* __restrict__ pos, int N, int K)
{
    extern __shared__ __align__(128) char sm[];
    const u32 sbuf = smem_u32(sm);
    const int tid = threadIdx.x, wid = tid >> 5, lid = tid & 31;
    const int wm = wid & 3, wn = wid >> 2;
    const int m0 = blockIdx.x * 128;
    const int n0 = blockIdx.y * 128;
    const int nk = K / GBK;

    float acc[2][8][4];
    #pragma unroll
    for (int t = 0; t < 2; t++)
        #pragma unroll
        for (int j = 0; j < 8; j++)
            #pragma unroll
            for (int q = 0; q < 4; q++) acc[t][j][q] = 0.f;

    auto ldtile = [&](const __nv_bfloat16* g, int row0, int kc, u32 sb){
        #pragma unroll
        for (int i = 0; i < 2; i++){
            int c = tid + i*256;
            int r = c >> 2, kg = c & 3;
            cpa16(sb + r*ASTRB + kg*16, g + (size_t)(row0 + r)*K + kc + kg*8);
        }
    };
    auto ldstage = [&](int kc, int s){
        u32 sb = sbuf + s*STAGEB;
        ldtile(Ahi, m0, kc, sb);
        ldtile(Alo, m0, kc, sb + TILEB);
        ldtile(Bhi, n0, kc, sb + 2*TILEB);
        ldtile(Blo, n0, kc, sb + 3*TILEB);
        cp_commit();
    };

    const u32 a_row = (u32)(wm*32 + (lid & 15));
    const u32 a_kb  = (u32)((lid >> 4) * 16);
    const u32 b_row = (u32)(wn*64 + ((lid >> 4) & 1)*8 + (lid & 7));
    const u32 b_kb  = (u32)(((lid >> 3) & 1) * 16);

    ldstage(0, 0);

    for (int kt = 0; kt < nk; kt++){
        if (kt + 1 < nk){ ldstage((kt + 1)*GBK, (kt + 1) & 1); cp_wait<1>(); }
        else cp_wait<0>();
        __syncthreads();

        u32 ab = sbuf + (kt & 1)*STAGEB;
        #pragma unroll
        for (int k16 = 0; k16 < 2; k16++){
            u32 kb = (u32)(k16 * 32);
            u32 ah[2][4], al[2][4];
            #pragma unroll
            for (int t = 0; t < 2; t++){
                u32 ad = ab + (a_row + t*16)*ASTRB + kb + a_kb;
                ldm_x4(ad, ah[t][0], ah[t][1], ah[t][2], ah[t][3]);
                ldm_x4(ad + TILEB, al[t][0], al[t][1], al[t][2], al[t][3]);
            }
            #pragma unroll
            for (int p = 0; p < 4; p++){
                u32 bd = ab + 2*TILEB + (b_row + p*16)*ASTRB + kb + b_kb;
                u32 h0, h1, h2, h3, l0, l1, l2, l3;
                ldm_x4(bd, h0, h1, h2, h3);
                ldm_x4(bd + TILEB, l0, l1, l2, l3);
                #pragma unroll
                for (int t = 0; t < 2; t++){
                    mma16816(acc[t][2*p],   ah[t], h0, h1);
                    mma16816(acc[t][2*p],   ah[t], l0, l1);
                    mma16816(acc[t][2*p],   al[t], h0, h1);
                    mma16816(acc[t][2*p+1], ah[t], h2, h3);
                    mma16816(acc[t][2*p+1], ah[t], l2, l3);
                    mma16816(acc[t][2*p+1], al[t], h2, h3);
                }
            }
        }
        __syncthreads();
    }

    // ---------------- epilogue ----------------
    const int mrow0 = m0 + wm*32 + (lid >> 2);
    const int colw = wn*64 + 2*(lid & 3);
    if (MODE == 0){
        #pragma unroll
        for (int t = 0; t < 2; t++)
            #pragma unroll
            for (int j = 0; j < 8; j++){
                int m = mrow0 + t*16;
                int nc = n0 + colw + j*8;
                *(float2*)&C[(size_t)m*N + nc]     = make_float2(acc[t][j][0], acc[t][j][1]);
                *(float2*)&C[(size_t)(m+8)*N + nc] = make_float2(acc[t][j][2], acc[t][j][3]);
            }
    } else {
        const int head = blockIdx.y;                    // BN == DH
        const float scale = 0.08838834764831845f;
        if (head < NQH + NKVH){
            const bool isq = head < NQH;
            __nv_bfloat16* dh = isq ? g_qh : g_kh;
            __nv_bfloat16* dl = isq ? g_ql : g_kl;
            const size_t rs = isq ? (size_t)QC : (size_t)KVC;
            const int hd = (isq ? head : head - NQH) * DH;
            #pragma unroll
            for (int t = 0; t < 2; t++){
                int m = mrow0 + t*16;
                int p0 = pos[m], p1 = pos[m + 8];
                #pragma unroll
                for (int j = 0; j < 8; j++){
                    int d = colw + j*8;
                    float invf = exp2f((float)(d >> 1) * (-13.287712379549449f / 64.f));
                    float s0, c0s, s1, c1s;
                    sincosf((float)p0 * invf, &s0, &c0s);
                    sincosf((float)p1 * invf, &s1, &c1s);
                    float x1 = acc[t][j][0], x2 = acc[t][j][1];
                    float o1 = x1*c0s - x2*s0, o2 = x2*c0s + x1*s0;
                    float y1 = acc[t][j][2], y2 = acc[t][j][3];
                    float u1 = y1*c1s - y2*s1, u2 = y2*c1s + y1*s1;
                    if (isq){ o1 *= scale; o2 *= scale; u1 *= scale; u2 *= scale; }
                    u32 hi, lo;
                    split2(o1, o2, hi, lo);
                    *(u32*)(dh + (size_t)m*rs + hd + d) = hi;
                    *(u32*)(dl + (size_t)m*rs + hd + d) = lo;
                    split2(u1, u2, hi, lo);
                    *(u32*)(dh + (size_t)(m+8)*rs + hd + d) = hi;
                    *(u32*)(dl + (size_t)(m+8)*rs + hd + d) = lo;
                }
            }
        } else {
            const int hd = (head - NQH - NKVH) * DH;
            #pragma unroll
            for (int t = 0; t < 2; t++)
                #pragma unroll
                for (int j = 0; j < 8; j++){
                    int m = mrow0 + t*16;
                    int d = colw + j*8;
                    u32 hi, lo;
                    split2(acc[t][j][0], acc[t][j][1], hi, lo);
                    *(u32*)(g_vh + (size_t)m*KVC + hd + d) = hi;
                    *(u32*)(g_vl + (size_t)m*KVC + hd + d) = lo;
                    split2(acc[t][j][2], acc[t][j][3], hi, lo);
                    *(u32*)(g_vh + (size_t)(m+8)*KVC + hd + d) = hi;
                    *(u32*)(g_vl + (size_t)(m+8)*KVC + hd + d) = lo;
                }
        }
    }
}

// =====================================================================
// Flash attention, HMMA bf16x3, causal, GQA.
// CTA: 128 q-rows, 8 warps (16 rows each). K/V tiles 64, double-buffered.
// Q hi-frags resident in regs; Q lo reloaded per k-step. Score frags feed
// PV directly as A-fragments (hi/lo split in-register). V via ldmatrix.trans.
// =====================================================================
#define RSTR 272                       // 128 bf16 row + 16B pad
#define QREG (128*RSTR)                // 34816 per Q array
#define KVT  (64*RSTR)                 // 17408 per K/V array
#define KVSTAGE (4*KVT)                // kh,kl,vh,vl = 69632
#define ATTN_SMEM (2*QREG + 2*KVSTAGE) // 208896

__global__ __launch_bounds__(256, 1)
void attn_kernel()
{
    extern __shared__ __align__(128) char smA[];
    const u32 sb = smem_u32(smA);
    const int tid = threadIdx.x, wid = tid >> 5, lid = tid & 31;
    const int qt = blockIdx.x, h = blockIdx.y, b = blockIdx.z;
    const int hk = h >> 2;
    const int q0 = qt * 128;
    const int nt = qt*2 + 2;

    // Q tile load (hi + lo): 4096 x 16B
    #pragma unroll
    for (int i = 0; i < 16; i++){
        int idx = tid + i*256;
        int arr = idx >> 11, rem = idx & 2047;
        int r = rem >> 4, ch = rem & 15;
        const __nv_bfloat16* src = (arr ? g_ql : g_qh)
            + (size_t)(b*SS + q0 + r)*QC + h*DH + ch*8;
        cpa16(sb + arr*QREG + r*RSTR + ch*16, src);
    }
    auto ldkv = [&](int k0, int s){
        #pragma unroll
        for (int i = 0; i < 16; i++){
            int idx = tid + i*256;
            int arr = idx >> 10, rem = idx & 1023;
            int r = rem >> 4, ch = rem & 15;
            const __nv_bfloat16* base = (arr == 0) ? g_kh : (arr == 1) ? g_kl
                                      : (arr == 2) ? g_vh : g_vl;
            cpa16(sb + 2*QREG + s*KVSTAGE + arr*KVT + r*RSTR + ch*16,
                  base + (size_t)(b*SS + k0 + r)*KVC + hk*DH + ch*8);
        }
    };
    ldkv(0, 0);
    cp_commit();                     // group: Q + KV0

    u32 qfh[8][4];
    float oacc[16][4];
    #pragma unroll
    for (int f = 0; f < 16; f++)
        #pragma unroll
        for (int q = 0; q < 4; q++) oacc[f][q] = 0.f;
    float mrow0 = -1e30f, mrow1 = -1e30f, lrow0 = 0.f, lrow1 = 0.f;

    // lane addressing
    const u32 a_base = (u32)((wid*16 + (lid & 15))*RSTR + (lid >> 4)*16);
    const u32 kb_row = (u32)((((lid >> 4) & 1)*8 + (lid & 7))*RSTR + ((lid >> 3) & 1)*16);
    const u32 vb_row = (u32)((((lid >> 3) & 1)*8 + (lid & 7))*RSTR + (lid >> 4)*16);

    for (int t = 0; t < nt; t++){
        if (t + 1 < nt){ ldkv((t + 1)*64, (t + 1) & 1); cp_commit(); cp_wait<1>(); }
        else cp_wait<0>();
        __syncthreads();

        if (t == 0){
            #pragma unroll
            for (int ks = 0; ks < 8; ks++){
                u32 ad = sb + a_base + ks*32;
                ldm_x4(ad, qfh[ks][0], qfh[ks][1], qfh[ks][2], qfh[ks][3]);
            }
        }

        const u32 kvb = sb + 2*QREG + (t & 1)*KVSTAGE;
        float s[8][4];
        #pragma unroll
        for (int f = 0; f < 8; f++)
            #pragma unroll
            for (int q = 0; q < 4; q++) s[f][q] = 0.f;

        // S = Q K^T
        #pragma unroll
        for (int ks = 0; ks < 8; ks++){
            u32 qfl[4];
            u32 qa = sb + QREG + a_base + ks*32;
            ldm_x4(qa, qfl[0], qfl[1], qfl[2], qfl[3]);
            #pragma unroll
            for (int p = 0; p < 4; p++){
                u32 ka = kvb + p*16*RSTR + kb_row + ks*32;
                u32 h0, h1, h2, h3, l0, l1, l2, l3;
                ldm_x4(ka, h0, h1, h2, h3);
                ldm_x4(ka + KVT, l0, l1, l2, l3);
                mma16816(s[2*p],   qfh[ks], h0, h1);
                mma16816(s[2*p],   qfh[ks], l0, l1);
                mma16816(s[2*p],   qfl,     h0, h1);
                mma16816(s[2*p+1], qfh[ks], h2, h3);
                mma16816(s[2*p+1], qfh[ks], l2, l3);
                mma16816(s[2*p+1], qfl,     h2, h3);
            }
        }

        // causal mask (only tiles near the diagonal)
        if (t >= nt - 2){
            int k0 = t*64;
            int qg0 = q0 + wid*16 + (lid >> 2);
            #pragma unroll
            for (int f = 0; f < 8; f++){
                int kgb = k0 + f*8 + (lid & 3)*2;
                if (kgb     > qg0) s[f][0] = -1e30f;
                if (kgb + 1 > qg0) s[f][1] = -1e30f;
                if (kgb     > qg0 + 8) s[f][2] = -1e30f;
                if (kgb + 1 > qg0 + 8) s[f][3] = -1e30f;
            }
        }

        // online softmax (rows r=lid>>2 and r+8; quad lanes share a row)
        float mx0 = -1e30f, mx1 = -1e30f;
        #pragma unroll
        for (int f = 0; f < 8; f++){
            mx0 = fmaxf(mx0, fmaxf(s[f][0], s[f][1]));
            mx1 = fmaxf(mx1, fmaxf(s[f][2], s[f][3]));
        }
        mx0 = fmaxf(mx0, __shfl_xor_sync(0xffffffffu, mx0, 1));
        mx0 = fmaxf(mx0, __shfl_xor_sync(0xffffffffu, mx0, 2));
        mx1 = fmaxf(mx1, __shfl_xor_sync(0xffffffffu, mx1, 1));
        mx1 = fmaxf(mx1, __shfl_xor_sync(0xffffffffu, mx1, 2));
        float mn0 = fmaxf(mrow0, mx0), mn1 = fmaxf(mrow1, mx1);
        float al0 = __expf(mrow0 - mn0), al1 = __expf(mrow1 - mn1);
        mrow0 = mn0; mrow1 = mn1;
        float rs0 = 0.f, rs1 = 0.f;
        #pragma unroll
        for (int f = 0; f < 8; f++){
            s[f][0] = __expf(s[f][0] - mn0); rs0 += s[f][0];
            s[f][1] = __expf(s[f][1] - mn0); rs0 += s[f][1];
            s[f][2] = __expf(s[f][2] - mn1); rs1 += s[f][2];
            s[f][3] = __expf(s[f][3] - mn1); rs1 += s[f][3];
        }
        rs0 += __shfl_xor_sync(0xffffffffu, rs0, 1);
        rs0 += __shfl_xor_sync(0xffffffffu, rs0, 2);
        rs1 += __shfl_xor_sync(0xffffffffu, rs1, 1);
        rs1 += __shfl_xor_sync(0xffffffffu, rs1, 2);
        lrow0 = lrow0*al0 + rs0;
        lrow1 = lrow1*al1 + rs1;
        #pragma unroll
        for (int f = 0; f < 16; f++){
            oacc[f][0] *= al0; oacc[f][1] *= al0;
            oacc[f][2] *= al1; oacc[f][3] *= al1;
        }

        // O += P V
        #pragma unroll
        for (int kk = 0; kk < 4; kk++){
            u32 ph[4], pl[4];
            split2(s[2*kk][0],   s[2*kk][1],   ph[0], pl[0]);
            split2(s[2*kk][2],   s[2*kk][3],   ph[1], pl[1]);
            split2(s[2*kk+1][0], s[2*kk+1][1], ph[2], pl[2]);
            split2(s[2*kk+1][2], s[2*kk+1][3], ph[3], pl[3]);
            #pragma unroll
            for (int p = 0; p < 8; p++){
                u32 va = kvb + 2*KVT + kk*16*RSTR + vb_row + p*32;
                u32 h0, h1, h2, h3, l0, l1, l2, l3;
                ldm_x4t(va, h0, h1, h2, h3);
                ldm_x4t(va + KVT, l0, l1, l2, l3);
                mma16816(oacc[2*p],   ph, h0, h1);
                mma16816(oacc[2*p],   ph, l0, l1);
                mma16816(oacc[2*p],   pl, h0, h1);
                mma16816(oacc[2*p+1], ph, h2, h3);
                mma16816(oacc[2*p+1], ph, l2, l3);
                mma16816(oacc[2*p+1], pl, h2, h3);
            }
        }
        __syncthreads();
    }

    // epilogue: divide by l, split, write aA hi/lo
    float inv0 = 1.f / lrow0, inv1 = 1.f / lrow1;
    const int row0 = q0 + wid*16 + (lid >> 2);
    const size_t tok0 = (size_t)(b*SS + row0);
    #pragma unroll
    for (int f = 0; f < 16; f++){
        int col = h*DH + f*8 + (lid & 3)*2;
        u32 hi, lo;
        split2(oacc[f][0]*inv0, oacc[f][1]*inv0, hi, lo);
        *(u32*)(g_aA_hi + tok0*QC + col) = hi;
        *(u32*)(g_aA_lo + tok0*QC + col) = lo;
        split2(oacc[f][2]*inv1, oacc[f][3]*inv1, hi, lo);
        *(u32*)(g_aA_hi + (tok0+8)*QC + col) = hi;
        *(u32*)(g_aA_lo + (tok0+8)*QC + col) = lo;
    }
}

// =====================================================================
extern "C" void kernel_launch(void* const* d_in, const int* in_sizes, int n_in,
                              void* d_out, int out_size)
{
    const float* hidden = (const float*)d_in[0];
    const float* wqkv   = (const float*)d_in[1];
    const float* wo     = (const float*)d_in[2];
    const int*   pos    = (const int*)d_in[3];
    float* out = (float*)d_out;

    void *p_hA_hi, *p_hA_lo, *p_wqkvT_hi, *p_wqkvT_lo;
    void *p_aA_hi, *p_aA_lo, *p_woT_hi, *p_woT_lo;
    cudaGetSymbolAddress(&p_hA_hi, g_hA_hi);
    cudaGetSymbolAddress(&p_hA_lo, g_hA_lo);
    cudaGetSymbolAddress(&p_wqkvT_hi, g_wqkvT_hi);
    cudaGetSymbolAddress(&p_wqkvT_lo, g_wqkvT_lo);
    cudaGetSymbolAddress(&p_aA_hi, g_aA_hi);
    cudaGetSymbolAddress(&p_aA_lo, g_aA_lo);
    cudaGetSymbolAddress(&p_woT_hi, g_woT_hi);
    cudaGetSymbolAddress(&p_woT_lo, g_woT_lo);

    cudaFuncSetAttribute(mma_gemm<1>, cudaFuncAttributeMaxDynamicSharedMemorySize, GSM);
    cudaFuncSetAttribute(mma_gemm<0>, cudaFuncAttributeMaxDynamicSharedMemorySize, GSM);
    cudaFuncSetAttribute(attn_kernel, cudaFuncAttributeMaxDynamicSharedMemorySize, ATTN_SMEM);

    // 1) split hidden into bf16 hi/lo
    {
        int n4 = (int)((size_t)MTOT * HH / 4);
        conv_split4<<<(n4 + 255)/256, 256>>>((const float4*)hidden,
                                             (ushort4*)p_hA_hi, (ushort4*)p_hA_lo, n4);
    }
    // 2) transpose+split weights -> [N][K] bf16 hi/lo
    conv_splitT<<<dim3(QKVN/32, HH/64), dim3(32, 8)>>>(
        wqkv, (__nv_bfloat16*)p_wqkvT_hi, (__nv_bfloat16*)p_wqkvT_lo, HH, QKVN);
    conv_splitT<<<dim3(HH/32, QC/64), dim3(32, 8)>>>(
        wo, (__nv_bfloat16*)p_woT_hi, (__nv_bfloat16*)p_woT_lo, QC, HH);

    // 3) QKV projection (HMMA bf16x3) + fused RoPE + bf16 hi/lo split epilogue
    mma_gemm<1><<<dim3(MTOT/128, QKVN/128), 256, GSM>>>(
        (const __nv_bfloat16*)p_hA_hi, (const __nv_bfloat16*)p_hA_lo,
        (const __nv_bfloat16*)p_wqkvT_hi, (const __nv_bfloat16*)p_wqkvT_lo,
        nullptr, pos, QKVN, HH);

    // 4) causal GQA flash attention (HMMA bf16x3) -> writes aA hi/lo
    attn_kernel<<<dim3(SS/128, NQH, NB), 256, ATTN_SMEM>>>();

    // 5) output projection (HMMA bf16x3)
    mma_gemm<0><<<dim3(MTOT/128, HH/128), 256, GSM>>>(
        (const __nv_bfloat16*)p_aA_hi, (const __nv_bfloat16*)p_aA_lo,
        (const __nv_bfloat16*)p_woT_hi, (const __nv_bfloat16*)p_woT_lo,
        out, nullptr, HH, QC);
}

// round 8
// speedup vs baseline: 2.6907x; 1.0234x over previous
#include <cuda_runtime.h>
#include <cuda_bf16.h>
#include <cuda_fp16.h>

// Problem constants
#define NB 2
#define SS 2048
#define HH 4096
#define NQH 32
#define NKVH 8
#define DH 128
#define MTOT (NB*SS)          // 4096 tokens
#define QC (NQH*DH)           // 4096
#define KVC (NKVH*DH)         // 1024
#define QKVN (QC + 2*KVC)     // 6144

typedef unsigned long long u64;
typedef unsigned int u32;
typedef unsigned short u16;

// ---------------- scratch (device globals; no allocation) ----------------
__device__ __nv_bfloat16 g_hA_hi[(size_t)MTOT*HH];
__device__ __nv_bfloat16 g_hA_lo[(size_t)MTOT*HH];
__device__ __nv_bfloat16 g_wqkvT_hi[(size_t)QKVN*HH];
__device__ __nv_bfloat16 g_wqkvT_lo[(size_t)QKVN*HH];
__device__ __nv_bfloat16 g_aA_hi[(size_t)MTOT*QC];
__device__ __nv_bfloat16 g_aA_lo[(size_t)MTOT*QC];
__device__ __nv_bfloat16 g_woT_hi[(size_t)HH*QC];
__device__ __nv_bfloat16 g_woT_lo[(size_t)HH*QC];
// Q/K bf16 hi/lo (Q pre-scaled + RoPE'd, K RoPE'd); V fp16 hi/lo
__device__ __nv_bfloat16 g_qh[(size_t)MTOT*QC];
__device__ __nv_bfloat16 g_ql[(size_t)MTOT*QC];
__device__ __nv_bfloat16 g_kh[(size_t)MTOT*KVC];
__device__ __nv_bfloat16 g_kl[(size_t)MTOT*KVC];
__device__ half          g_vh[(size_t)MTOT*KVC];
__device__ half          g_vl[(size_t)MTOT*KVC];

// ---------------- PTX helpers ----------------
__device__ __forceinline__ u32 smem_u32(const void* p){
    u32 a; asm("{ .reg .u64 t; cvta.to.shared.u64 t, %1; cvt.u32.u64 %0, t; }" : "=r"(a) : "l"(p));
    return a;
}
__device__ __forceinline__ void cpa16(u32 s, const void* g){
    asm volatile("cp.async.cg.shared.global [%0], [%1], 16;" :: "r"(s), "l"(g));
}
__device__ __forceinline__ void cp_commit(){ asm volatile("cp.async.commit_group;"); }
template<int N> __device__ __forceinline__ void cp_wait(){
    asm volatile("cp.async.wait_group %0;" :: "n"(N));
}
__device__ __forceinline__ void ldm_x4(u32 addr, u32& r0, u32& r1, u32& r2, u32& r3){
    asm volatile("ldmatrix.sync.aligned.m8n8.x4.shared.b16 {%0,%1,%2,%3}, [%4];"
                 : "=r"(r0), "=r"(r1), "=r"(r2), "=r"(r3) : "r"(addr));
}
__device__ __forceinline__ void ldm_x4t(u32 addr, u32& r0, u32& r1, u32& r2, u32& r3){
    asm volatile("ldmatrix.sync.aligned.m8n8.x4.trans.shared.b16 {%0,%1,%2,%3}, [%4];"
                 : "=r"(r0), "=r"(r1), "=r"(r2), "=r"(r3) : "r"(addr));
}
__device__ __forceinline__ void mma16816(float* c, const u32* a, u32 b0, u32 b1){
    asm volatile("mma.sync.aligned.m16n8k16.row.col.f32.bf16.bf16.f32 "
                 "{%0,%1,%2,%3}, {%4,%5,%6,%7}, {%8,%9}, {%0,%1,%2,%3};"
                 : "+f"(c[0]), "+f"(c[1]), "+f"(c[2]), "+f"(c[3])
                 : "r"(a[0]), "r"(a[1]), "r"(a[2]), "r"(a[3]), "r"(b0), "r"(b1));
}
__device__ __forceinline__ void mma16816h(float* c, const u32* a, u32 b0, u32 b1){
    asm volatile("mma.sync.aligned.m16n8k16.row.col.f32.f16.f16.f32 "
                 "{%0,%1,%2,%3}, {%4,%5,%6,%7}, {%8,%9}, {%0,%1,%2,%3};"
                 : "+f"(c[0]), "+f"(c[1]), "+f"(c[2]), "+f"(c[3])
                 : "r"(a[0]), "r"(a[1]), "r"(a[2]), "r"(a[3]), "r"(b0), "r"(b1));
}
// split two fp32 into packed bf16 hi-pair + lo-pair
__device__ __forceinline__ void split2(float x0, float x1, u32& hi, u32& lo){
    __nv_bfloat16 h0 = __float2bfloat16(x0), h1 = __float2bfloat16(x1);
    hi = (u32)__bfloat16_as_ushort(h0) | ((u32)__bfloat16_as_ushort(h1) << 16);
    __nv_bfloat16 l0 = __float2bfloat16(x0 - __bfloat162float(h0));
    __nv_bfloat16 l1 = __float2bfloat16(x1 - __bfloat162float(h1));
    lo = (u32)__bfloat16_as_ushort(l0) | ((u32)__bfloat16_as_ushort(l1) << 16);
}
// split two fp32 into packed fp16 hi-pair + lo-pair
__device__ __forceinline__ void split2h(float x0, float x1, u32& hi, u32& lo){
    half h0 = __float2half_rn(x0), h1 = __float2half_rn(x1);
    hi = (u32)__half_as_ushort(h0) | ((u32)__half_as_ushort(h1) << 16);
    half l0 = __float2half_rn(x0 - __half2float(h0));
    half l1 = __float2half_rn(x1 - __half2float(h1));
    lo = (u32)__half_as_ushort(l0) | ((u32)__half_as_ushort(l1) << 16);
}
__device__ __forceinline__ u32 packh2(float x0, float x1){
    half2 h = __floats2half2_rn(x0, x1);
    return *(u32*)&h;
}

// =====================================================================
// Split-convert kernels
// =====================================================================
__global__ void conv_split4(const float4* __restrict__ src,
                            ushort4* __restrict__ hi, ushort4* __restrict__ lo, int n4)
{
    int i = blockIdx.x * blockDim.x + threadIdx.x;
    if (i >= n4) return;
    float4 x = src[i];
    __nv_bfloat16 h0 = __float2bfloat16(x.x), h1 = __float2bfloat16(x.y);
    __nv_bfloat16 h2 = __float2bfloat16(x.z), h3 = __float2bfloat16(x.w);
    hi[i] = make_ushort4(__bfloat16_as_ushort(h0), __bfloat16_as_ushort(h1),
                         __bfloat16_as_ushort(h2), __bfloat16_as_ushort(h3));
    __nv_bfloat16 l0 = __float2bfloat16(x.x - __bfloat162float(h0));
    __nv_bfloat16 l1 = __float2bfloat16(x.y - __bfloat162float(h1));
    __nv_bfloat16 l2 = __float2bfloat16(x.z - __bfloat162float(h2));
    __nv_bfloat16 l3 = __float2bfloat16(x.w - __bfloat162float(h3));
    lo[i] = make_ushort4(__bfloat16_as_ushort(l0), __bfloat16_as_ushort(l1),
                         __bfloat16_as_ushort(l2), __bfloat16_as_ushort(l3));
}

__global__ void conv_splitT(const float* __restrict__ src,
                            __nv_bfloat16* __restrict__ hiT, __nv_bfloat16* __restrict__ loT,
                            int R, int Cc)
{
    __shared__ float t[64][33];
    int r0 = blockIdx.y * 64, c0 = blockIdx.x * 32;
    int tx = threadIdx.x, ty = threadIdx.y;  // (32,8)
    #pragma unroll
    for (int i = 0; i < 8; i++){
        int r = ty + i*8;
        t[r][tx] = src[(size_t)(r0 + r) * Cc + c0 + tx];
    }
    __syncthreads();
    #pragma unroll
    for (int i = 0; i < 4; i++){
        int cc = ty + i*8;
        float x0 = t[tx*2][cc], x1 = t[tx*2+1][cc];
        __nv_bfloat16 h0 = __float2bfloat16(x0), h1 = __float2bfloat16(x1);
        __nv_bfloat162 hv; hv.x = h0; hv.y = h1;
        __nv_bfloat162 lv;
        lv.x = __float2bfloat16(x0 - __bfloat162float(h0));
        lv.y = __float2bfloat16(x1 - __bfloat162float(h1));
        size_t o = (size_t)(c0 + cc) * R + r0 + tx*2;
        *(__nv_bfloat162*)(hiT + o) = hv;
        *(__nv_bfloat162*)(loT + o) = lv;
    }
}

// =====================================================================
// HMMA bf16x3 GEMM: C[M,N] = A[M,K] * B[N,K]^T.
// 128x128 CTA tile, BK=32, 8 warps (32x64 each), cp.async double buffer.
// 2 CTAs/SM. MODE 1: epilogue -> Q/K bf16 hi/lo + V fp16 hi/lo w/ RoPE.
// MODE 0: C fp32.
// =====================================================================
#define GBK 32
#define ASTRB 80
#define TILEB (128*ASTRB)
#define STAGEB (4*TILEB)
#define GSM (2*STAGEB)                 // 81920 B

template<int MODE>
__global__ __launch_bounds__(256, 2)
void mma_gemm(const __nv_bfloat16* __restrict__ Ahi, const __nv_bfloat16* __restrict__ Alo,
              const __nv_bfloat16* __restrict__ Bhi, const __nv_bfloat16* __restrict__ Blo,
              float* __restrict__ C, const int* __restrict__ pos, int N, int K)
{
    extern __shared__ __align__(128) char sm[];
    const u32 sbuf = smem_u32(sm);
    const int tid = threadIdx.x, wid = tid >> 5, lid = tid & 31;
    const int wm = wid & 3, wn = wid >> 2;
    const int m0 = blockIdx.x * 128;
    const int n0 = blockIdx.y * 128;
    const int nk = K / GBK;

    float acc[2][8][4];
    #pragma unroll
    for (int t = 0; t < 2; t++)
        #pragma unroll
        for (int j = 0; j < 8; j++)
            #pragma unroll
            for (int q = 0; q < 4; q++) acc[t][j][q] = 0.f;

    auto ldtile = [&](const __nv_bfloat16* g, int row0, int kc, u32 sb){
        #pragma unroll
        for (int i = 0; i < 2; i++){
            int c = tid + i*256;
            int r = c >> 2, kg = c & 3;
            cpa16(sb + r*ASTRB + kg*16, g + (size_t)(row0 + r)*K + kc + kg*8);
        }
    };
    auto ldstage = [&](int kc, int s){
        u32 sb = sbuf + s*STAGEB;
        ldtile(Ahi, m0, kc, sb);
        ldtile(Alo, m0, kc, sb + TILEB);
        ldtile(Bhi, n0, kc, sb + 2*TILEB);
        ldtile(Blo, n0, kc, sb + 3*TILEB);
        cp_commit();
    };

    const u32 a_row = (u32)(wm*32 + (lid & 15));
    const u32 a_kb  = (u32)((lid >> 4) * 16);
    const u32 b_row = (u32)(wn*64 + ((lid >> 4) & 1)*8 + (lid & 7));
    const u32 b_kb  = (u32)(((lid >> 3) & 1) * 16);

    ldstage(0, 0);

    for (int kt = 0; kt < nk; kt++){
        if (kt + 1 < nk){ ldstage((kt + 1)*GBK, (kt + 1) & 1); cp_wait<1>(); }
        else cp_wait<0>();
        __syncthreads();

        u32 ab = sbuf + (kt & 1)*STAGEB;
        #pragma unroll
        for (int k16 = 0; k16 < 2; k16++){
            u32 kb = (u32)(k16 * 32);
            u32 ah[2][4], al[2][4];
            #pragma unroll
            for (int t = 0; t < 2; t++){
                u32 ad = ab + (a_row + t*16)*ASTRB + kb + a_kb;
                ldm_x4(ad, ah[t][0], ah[t][1], ah[t][2], ah[t][3]);
                ldm_x4(ad + TILEB, al[t][0], al[t][1], al[t][2], al[t][3]);
            }
            #pragma unroll
            for (int p = 0; p < 4; p++){
                u32 bd = ab + 2*TILEB + (b_row + p*16)*ASTRB + kb + b_kb;
                u32 h0, h1, h2, h3, l0, l1, l2, l3;
                ldm_x4(bd, h0, h1, h2, h3);
                ldm_x4(bd + TILEB, l0, l1, l2, l3);
                #pragma unroll
                for (int t = 0; t < 2; t++){
                    mma16816(acc[t][2*p],   ah[t], h0, h1);
                    mma16816(acc[t][2*p],   ah[t], l0, l1);
                    mma16816(acc[t][2*p],   al[t], h0, h1);
                    mma16816(acc[t][2*p+1], ah[t], h2, h3);
                    mma16816(acc[t][2*p+1], ah[t], l2, l3);
                    mma16816(acc[t][2*p+1], al[t], h2, h3);
                }
            }
        }
        __syncthreads();
    }

    // ---------------- epilogue ----------------
    const int mrow0 = m0 + wm*32 + (lid >> 2);
    const int colw = wn*64 + 2*(lid & 3);
    if (MODE == 0){
        #pragma unroll
        for (int t = 0; t < 2; t++)
            #pragma unroll
            for (int j = 0; j < 8; j++){
                int m = mrow0 + t*16;
                int nc = n0 + colw + j*8;
                *(float2*)&C[(size_t)m*N + nc]     = make_float2(acc[t][j][0], acc[t][j][1]);
                *(float2*)&C[(size_t)(m+8)*N + nc] = make_float2(acc[t][j][2], acc[t][j][3]);
            }
    } else {
        const int head = blockIdx.y;                    // BN == DH
        const float scale = 0.08838834764831845f;
        if (head < NQH + NKVH){
            const bool isq = head < NQH;
            __nv_bfloat16* dh = isq ? g_qh : g_kh;
            __nv_bfloat16* dl = isq ? g_ql : g_kl;
            const size_t rs = isq ? (size_t)QC : (size_t)KVC;
            const int hd = (isq ? head : head - NQH) * DH;
            #pragma unroll
            for (int t = 0; t < 2; t++){
                int m = mrow0 + t*16;
                int p0 = pos[m], p1 = pos[m + 8];
                #pragma unroll
                for (int j = 0; j < 8; j++){
                    int d = colw + j*8;
                    float invf = exp2f((float)(d >> 1) * (-13.287712379549449f / 64.f));
                    float s0, c0s, s1, c1s;
                    sincosf((float)p0 * invf, &s0, &c0s);
                    sincosf((float)p1 * invf, &s1, &c1s);
                    float x1 = acc[t][j][0], x2 = acc[t][j][1];
                    float o1 = x1*c0s - x2*s0, o2 = x2*c0s + x1*s0;
                    float y1 = acc[t][j][2], y2 = acc[t][j][3];
                    float u1 = y1*c1s - y2*s1, u2 = y2*c1s + y1*s1;
                    if (isq){ o1 *= scale; o2 *= scale; u1 *= scale; u2 *= scale; }
                    u32 hi, lo;
                    split2(o1, o2, hi, lo);
                    *(u32*)(dh + (size_t)m*rs + hd + d) = hi;
                    *(u32*)(dl + (size_t)m*rs + hd + d) = lo;
                    split2(u1, u2, hi, lo);
                    *(u32*)(dh + (size_t)(m+8)*rs + hd + d) = hi;
                    *(u32*)(dl + (size_t)(m+8)*rs + hd + d) = lo;
                }
            }
        } else {
            const int hd = (head - NQH - NKVH) * DH;
            #pragma unroll
            for (int t = 0; t < 2; t++)
                #pragma unroll
                for (int j = 0; j < 8; j++){
                    int m = mrow0 + t*16;
                    int d = colw + j*8;
                    u32 hi, lo;
                    split2h(acc[t][j][0], acc[t][j][1], hi, lo);
                    *(u32*)(g_vh + (size_t)m*KVC + hd + d) = hi;
                    *(u32*)(g_vl + (size_t)m*KVC + hd + d) = lo;
                    split2h(acc[t][j][2], acc[t][j][3], hi, lo);
                    *(u32*)(g_vh + (size_t)(m+8)*KVC + hd + d) = hi;
                    *(u32*)(g_vl + (size_t)(m+8)*KVC + hd + d) = lo;
                }
        }
    }
}

// =====================================================================
// Flash attention: QK = bf16x3 HMMA, PV = fp16x2 HMMA (P as single fp16,
// V as fp16 hi+lo). Q hi+lo frags register-resident. Long blocks first.
// =====================================================================
#define RSTR 272                       // 128 x 2B row + 16B pad
#define QREG (128*RSTR)                // 34816 per Q array
#define KVT  (64*RSTR)                 // 17408 per K/V array
#define KVSTAGE (4*KVT)                // kh,kl,vh,vl = 69632
#define ATTN_SMEM (2*QREG + 2*KVSTAGE) // 208896

__global__ __launch_bounds__(256, 1)
void attn_kernel()
{
    extern __shared__ __align__(128) char smA[];
    const u32 sb = smem_u32(smA);
    const int tid = threadIdx.x, wid = tid >> 5, lid = tid & 31;
    const int qt = gridDim.x - 1 - blockIdx.x;      // long blocks first
    const int h = blockIdx.y, b = blockIdx.z;
    const int hk = h >> 2;
    const int q0 = qt * 128;
    const int nt = qt*2 + 2;

    // Q tile load (hi + lo): 4096 x 16B
    #pragma unroll
    for (int i = 0; i < 16; i++){
        int idx = tid + i*256;
        int arr = idx >> 11, rem = idx & 2047;
        int r = rem >> 4, ch = rem & 15;
        const __nv_bfloat16* src = (arr ? g_ql : g_qh)
            + (size_t)(b*SS + q0 + r)*QC + h*DH + ch*8;
        cpa16(sb + arr*QREG + r*RSTR + ch*16, src);
    }
    auto ldkv = [&](int k0, int s){
        #pragma unroll
        for (int i = 0; i < 16; i++){
            int idx = tid + i*256;
            int arr = idx >> 10, rem = idx & 1023;
            int r = rem >> 4, ch = rem & 15;
            const char* base = (arr == 0) ? (const char*)g_kh
                             : (arr == 1) ? (const char*)g_kl
                             : (arr == 2) ? (const char*)g_vh : (const char*)g_vl;
            cpa16(sb + 2*QREG + s*KVSTAGE + arr*KVT + r*RSTR + ch*16,
                  base + ((size_t)(b*SS + k0 + r)*KVC + hk*DH + ch*8)*2);
        }
    };
    ldkv(0, 0);
    cp_commit();                     // group: Q + KV0

    u32 qfh[8][4], qfl[8][4];
    float oacc[16][4];
    #pragma unroll
    for (int f = 0; f < 16; f++)
        #pragma unroll
        for (int q = 0; q < 4; q++) oacc[f][q] = 0.f;
    float mrow0 = -1e30f, mrow1 = -1e30f, lrow0 = 0.f, lrow1 = 0.f;

    const u32 a_base = (u32)((wid*16 + (lid & 15))*RSTR + (lid >> 4)*16);
    const u32 kb_row = (u32)((((lid >> 4) & 1)*8 + (lid & 7))*RSTR + ((lid >> 3) & 1)*16);
    const u32 vb_row = (u32)((((lid >> 3) & 1)*8 + (lid & 7))*RSTR + (lid >> 4)*16);

    for (int t = 0; t < nt; t++){
        if (t + 1 < nt){ ldkv((t + 1)*64, (t + 1) & 1); cp_commit(); cp_wait<1>(); }
        else cp_wait<0>();
        __syncthreads();

        if (t == 0){
            #pragma unroll
            for (int ks = 0; ks < 8; ks++){
                u32 ad = sb + a_base + ks*32;
                ldm_x4(ad, qfh[ks][0], qfh[ks][1], qfh[ks][2], qfh[ks][3]);
                ldm_x4(ad + QREG, qfl[ks][0], qfl[ks][1], qfl[ks][2], qfl[ks][3]);
            }
        }

        const u32 kvb = sb + 2*QREG + (t & 1)*KVSTAGE;
        float s[8][4];
        #pragma unroll
        for (int f = 0; f < 8; f++)
            #pragma unroll
            for (int q = 0; q < 4; q++) s[f][q] = 0.f;

        // S = Q K^T (bf16 x3)
        #pragma unroll
        for (int ks = 0; ks < 8; ks++){
            #pragma unroll
            for (int p = 0; p < 4; p++){
                u32 ka = kvb + p*16*RSTR + kb_row + ks*32;
                u32 h0, h1, h2, h3, l0, l1, l2, l3;
                ldm_x4(ka, h0, h1, h2, h3);
                ldm_x4(ka + KVT, l0, l1, l2, l3);
                mma16816(s[2*p],   qfh[ks], h0, h1);
                mma16816(s[2*p],   qfh[ks], l0, l1);
                mma16816(s[2*p],   qfl[ks], h0, h1);
                mma16816(s[2*p+1], qfh[ks], h2, h3);
                mma16816(s[2*p+1], qfh[ks], l2, l3);
                mma16816(s[2*p+1], qfl[ks], h2, h3);
            }
        }

        // causal mask (tiles near diagonal)
        if (t >= nt - 2){
            int k0 = t*64;
            int qg0 = q0 + wid*16 + (lid >> 2);
            #pragma unroll
            for (int f = 0; f < 8; f++){
                int kgb = k0 + f*8 + (lid & 3)*2;
                if (kgb     > qg0) s[f][0] = -1e30f;
                if (kgb + 1 > qg0) s[f][1] = -1e30f;
                if (kgb     > qg0 + 8) s[f][2] = -1e30f;
                if (kgb + 1 > qg0 + 8) s[f][3] = -1e30f;
            }
        }

        // online softmax
        float mx0 = -1e30f, mx1 = -1e30f;
        #pragma unroll
        for (int f = 0; f < 8; f++){
            mx0 = fmaxf(mx0, fmaxf(s[f][0], s[f][1]));
            mx1 = fmaxf(mx1, fmaxf(s[f][2], s[f][3]));
        }
        mx0 = fmaxf(mx0, __shfl_xor_sync(0xffffffffu, mx0, 1));
        mx0 = fmaxf(mx0, __shfl_xor_sync(0xffffffffu, mx0, 2));
        mx1 = fmaxf(mx1, __shfl_xor_sync(0xffffffffu, mx1, 1));
        mx1 = fmaxf(mx1, __shfl_xor_sync(0xffffffffu, mx1, 2));
        float mn0 = fmaxf(mrow0, mx0), mn1 = fmaxf(mrow1, mx1);
        float al0 = __expf(mrow0 - mn0), al1 = __expf(mrow1 - mn1);
        mrow0 = mn0; mrow1 = mn1;
        float rs0 = 0.f, rs1 = 0.f;
        #pragma unroll
        for (int f = 0; f < 8; f++){
            s[f][0] = __expf(s[f][0] - mn0); rs0 += s[f][0];
            s[f][1] = __expf(s[f][1] - mn0); rs0 += s[f][1];
            s[f][2] = __expf(s[f][2] - mn1); rs1 += s[f][2];
            s[f][3] = __expf(s[f][3] - mn1); rs1 += s[f][3];
        }
        rs0 += __shfl_xor_sync(0xffffffffu, rs0, 1);
        rs0 += __shfl_xor_sync(0xffffffffu, rs0, 2);
        rs1 += __shfl_xor_sync(0xffffffffu, rs1, 1);
        rs1 += __shfl_xor_sync(0xffffffffu, rs1, 2);
        lrow0 = lrow0*al0 + rs0;
        lrow1 = lrow1*al1 + rs1;
        #pragma unroll
        for (int f = 0; f < 16; f++){
            oacc[f][0] *= al0; oacc[f][1] *= al0;
            oacc[f][2] *= al1; oacc[f][3] *= al1;
        }

        // O += P V  (P single fp16, V fp16 hi+lo)
        #pragma unroll
        for (int kk = 0; kk < 4; kk++){
            u32 ph[4];
            ph[0] = packh2(s[2*kk][0],   s[2*kk][1]);
            ph[1] = packh2(s[2*kk][2],   s[2*kk][3]);
            ph[2] = packh2(s[2*kk+1][0], s[2*kk+1][1]);
            ph[3] = packh2(s[2*kk+1][2], s[2*kk+1][3]);
            #pragma unroll
            for (int p = 0; p < 8; p++){
                u32 va = kvb + 2*KVT + kk*16*RSTR + vb_row + p*32;
                u32 h0, h1, h2, h3, l0, l1, l2, l3;
                ldm_x4t(va, h0, h1, h2, h3);
                ldm_x4t(va + KVT, l0, l1, l2, l3);
                mma16816h(oacc[2*p],   ph, h0, h1);
                mma16816h(oacc[2*p],   ph, l0, l1);
                mma16816h(oacc[2*p+1], ph, h2, h3);
                mma16816h(oacc[2*p+1], ph, l2, l3);
            }
        }
        __syncthreads();
    }

    // epilogue
    float inv0 = 1.f / lrow0, inv1 = 1.f / lrow1;
    const int row0 = q0 + wid*16 + (lid >> 2);
    const size_t tok0 = (size_t)(b*SS + row0);
    #pragma unroll
    for (int f = 0; f < 16; f++){
        int col = h*DH + f*8 + (lid & 3)*2;
        u32 hi, lo;
        split2(oacc[f][0]*inv0, oacc[f][1]*inv0, hi, lo);
        *(u32*)(g_aA_hi + tok0*QC + col) = hi;
        *(u32*)(g_aA_lo + tok0*QC + col) = lo;
        split2(oacc[f][2]*inv1, oacc[f][3]*inv1, hi, lo);
        *(u32*)(g_aA_hi + (tok0+8)*QC + col) = hi;
        *(u32*)(g_aA_lo + (tok0+8)*QC + col) = lo;
    }
}

// =====================================================================
extern "C" void kernel_launch(void* const* d_in, const int* in_sizes, int n_in,
                              void* d_out, int out_size)
{
    const float* hidden = (const float*)d_in[0];
    const float* wqkv   = (const float*)d_in[1];
    const float* wo     = (const float*)d_in[2];
    const int*   pos    = (const int*)d_in[3];
    float* out = (float*)d_out;

    void *p_hA_hi, *p_hA_lo, *p_wqkvT_hi, *p_wqkvT_lo;
    void *p_aA_hi, *p_aA_lo, *p_woT_hi, *p_woT_lo;
    cudaGetSymbolAddress(&p_hA_hi, g_hA_hi);
    cudaGetSymbolAddress(&p_hA_lo, g_hA_lo);
    cudaGetSymbolAddress(&p_wqkvT_hi, g_wqkvT_hi);
    cudaGetSymbolAddress(&p_wqkvT_lo, g_wqkvT_lo);
    cudaGetSymbolAddress(&p_aA_hi, g_aA_hi);
    cudaGetSymbolAddress(&p_aA_lo, g_aA_lo);
    cudaGetSymbolAddress(&p_woT_hi, g_woT_hi);
    cudaGetSymbolAddress(&p_woT_lo, g_woT_lo);

    cudaFuncSetAttribute(mma_gemm<1>, cudaFuncAttributeMaxDynamicSharedMemorySize, GSM);
    cudaFuncSetAttribute(mma_gemm<0>, cudaFuncAttributeMaxDynamicSharedMemorySize, GSM);
    cudaFuncSetAttribute(attn_kernel, cudaFuncAttributeMaxDynamicSharedMemorySize, ATTN_SMEM);

    // 1) split hidden into bf16 hi/lo
    {
        int n4 = (int)((size_t)MTOT * HH / 4);
        conv_split4<<<(n4 + 255)/256, 256>>>((const float4*)hidden,
                                             (ushort4*)p_hA_hi, (ushort4*)p_hA_lo, n4);
    }
    // 2) transpose+split weights -> [N][K] bf16 hi/lo
    conv_splitT<<<dim3(QKVN/32, HH/64), dim3(32, 8)>>>(
        wqkv, (__nv_bfloat16*)p_wqkvT_hi, (__nv_bfloat16*)p_wqkvT_lo, HH, QKVN);
    conv_splitT<<<dim3(HH/32, QC/64), dim3(32, 8)>>>(
        wo, (__nv_bfloat16*)p_woT_hi, (__nv_bfloat16*)p_woT_lo, QC, HH);

    // 3) QKV projection (HMMA bf16x3) + fused RoPE + split epilogue
    mma_gemm<1><<<dim3(MTOT/128, QKVN/128), 256, GSM>>>(
        (const __nv_bfloat16*)p_hA_hi, (const __nv_bfloat16*)p_hA_lo,
        (const __nv_bfloat16*)p_wqkvT_hi, (const __nv_bfloat16*)p_wqkvT_lo,
        nullptr, pos, QKVN, HH);

    // 4) causal GQA flash attention -> writes aA hi/lo
    attn_kernel<<<dim3(SS/128, NQH, NB), 256, ATTN_SMEM>>>();

    // 5) output projection (HMMA bf16x3)
    mma_gemm<0><<<dim3(MTOT/128, HH/128), 256, GSM>>>(
        (const __nv_bfloat16*)p_aA_hi, (const __nv_bfloat16*)p_aA_lo,
        (const __nv_bfloat16*)p_woT_hi, (const __nv_bfloat16*)p_woT_lo,
        out, nullptr, HH, QC);
}

// round 9
// speedup vs baseline: 3.7331x; 1.3874x over previous
#include <cuda_runtime.h>
#include <cuda_fp16.h>

// Problem constants
#define NB 2
#define SS 2048
#define HH 4096
#define NQH 32
#define NKVH 8
#define DH 128
#define MTOT (NB*SS)          // 4096 tokens
#define QC (NQH*DH)           // 4096
#define KVC (NKVH*DH)         // 1024
#define QKVN (QC + 2*KVC)     // 6144

typedef unsigned long long u64;
typedef unsigned int u32;

// ---------------- scratch (device globals; no allocation) ----------------
__device__ half g_hA_hi[(size_t)MTOT*HH];     // hidden fp16 hi
__device__ half g_hA_lo[(size_t)MTOT*HH];     // hidden fp16 residual
__device__ half g_wqkvT[(size_t)QKVN*HH];     // w_qkv^T single fp16
__device__ half g_aA_hi[(size_t)MTOT*QC];     // attn out fp16 hi
__device__ half g_aA_lo[(size_t)MTOT*QC];
__device__ half g_woT[(size_t)HH*QC];         // w_o^T single fp16
__device__ half g_qh[(size_t)MTOT*QC];        // Q fp16 hi (scaled+RoPE)
__device__ half g_ql[(size_t)MTOT*QC];        // Q fp16 residual
__device__ half g_kh[(size_t)MTOT*KVC];       // K single fp16 (RoPE)
__device__ half g_vh[(size_t)MTOT*KVC];       // V single fp16

// ---------------- PTX helpers ----------------
__device__ __forceinline__ u32 smem_u32(const void* p){
    u32 a; asm("{ .reg .u64 t; cvta.to.shared.u64 t, %1; cvt.u32.u64 %0, t; }" : "=r"(a) : "l"(p));
    return a;
}
__device__ __forceinline__ void cpa16(u32 s, const void* g){
    asm volatile("cp.async.cg.shared.global [%0], [%1], 16;" :: "r"(s), "l"(g));
}
__device__ __forceinline__ void cp_commit(){ asm volatile("cp.async.commit_group;"); }
template<int N> __device__ __forceinline__ void cp_wait(){
    asm volatile("cp.async.wait_group %0;" :: "n"(N));
}
__device__ __forceinline__ void ldm_x4(u32 addr, u32& r0, u32& r1, u32& r2, u32& r3){
    asm volatile("ldmatrix.sync.aligned.m8n8.x4.shared.b16 {%0,%1,%2,%3}, [%4];"
                 : "=r"(r0), "=r"(r1), "=r"(r2), "=r"(r3) : "r"(addr));
}
__device__ __forceinline__ void ldm_x4t(u32 addr, u32& r0, u32& r1, u32& r2, u32& r3){
    asm volatile("ldmatrix.sync.aligned.m8n8.x4.trans.shared.b16 {%0,%1,%2,%3}, [%4];"
                 : "=r"(r0), "=r"(r1), "=r"(r2), "=r"(r3) : "r"(addr));
}
__device__ __forceinline__ void mma16816h(float* c, const u32* a, u32 b0, u32 b1){
    asm volatile("mma.sync.aligned.m16n8k16.row.col.f32.f16.f16.f32 "
                 "{%0,%1,%2,%3}, {%4,%5,%6,%7}, {%8,%9}, {%0,%1,%2,%3};"
                 : "+f"(c[0]), "+f"(c[1]), "+f"(c[2]), "+f"(c[3])
                 : "r"(a[0]), "r"(a[1]), "r"(a[2]), "r"(a[3]), "r"(b0), "r"(b1));
}
// split two fp32 into packed fp16 hi-pair + residual-pair
__device__ __forceinline__ void split2h(float x0, float x1, u32& hi, u32& lo){
    half h0 = __float2half_rn(x0), h1 = __float2half_rn(x1);
    hi = (u32)__half_as_ushort(h0) | ((u32)__half_as_ushort(h1) << 16);
    half l0 = __float2half_rn(x0 - __half2float(h0));
    half l1 = __float2half_rn(x1 - __half2float(h1));
    lo = (u32)__half_as_ushort(l0) | ((u32)__half_as_ushort(l1) << 16);
}
__device__ __forceinline__ u32 packh2(float x0, float x1){
    half2 h = __floats2half2_rn(x0, x1);
    return *(u32*)&h;
}

// =====================================================================
// Convert kernels
// =====================================================================
__global__ void conv_split4(const float4* __restrict__ src,
                            ushort4* __restrict__ hi, ushort4* __restrict__ lo, int n4)
{
    int i = blockIdx.x * blockDim.x + threadIdx.x;
    if (i >= n4) return;
    float4 x = src[i];
    half h0 = __float2half_rn(x.x), h1 = __float2half_rn(x.y);
    half h2 = __float2half_rn(x.z), h3 = __float2half_rn(x.w);
    hi[i] = make_ushort4(__half_as_ushort(h0), __half_as_ushort(h1),
                         __half_as_ushort(h2), __half_as_ushort(h3));
    half l0 = __float2half_rn(x.x - __half2float(h0));
    half l1 = __float2half_rn(x.y - __half2float(h1));
    half l2 = __float2half_rn(x.z - __half2float(h2));
    half l3 = __float2half_rn(x.w - __half2float(h3));
    lo[i] = make_ushort4(__half_as_ushort(l0), __half_as_ushort(l1),
                         __half_as_ushort(l2), __half_as_ushort(l3));
}

// transpose + convert: src[R][C] fp32 -> dst[C][R] single fp16
__global__ void convT(const float* __restrict__ src, half* __restrict__ dstT,
                      int R, int Cc)
{
    __shared__ float t[64][33];
    int r0 = blockIdx.y * 64, c0 = blockIdx.x * 32;
    int tx = threadIdx.x, ty = threadIdx.y;  // (32,8)
    #pragma unroll
    for (int i = 0; i < 8; i++){
        int r = ty + i*8;
        t[r][tx] = src[(size_t)(r0 + r) * Cc + c0 + tx];
    }
    __syncthreads();
    #pragma unroll
    for (int i = 0; i < 4; i++){
        int cc = ty + i*8;
        half2 hv = __floats2half2_rn(t[tx*2][cc], t[tx*2+1][cc]);
        *(half2*)(dstT + (size_t)(c0 + cc) * R + r0 + tx*2) = hv;
    }
}

// =====================================================================
// HMMA fp16x2 GEMM: C[M,N] = (Ah+Al)[M,K] * B[N,K]^T  (B single fp16).
// 128x128 CTA tile, BK=32, 8 warps (32x64 each), cp.async 3-stage.
// 2 CTAs/SM. MODE 1: epilogue -> Q hi/lo + K,V single fp16 w/ RoPE.
// MODE 0: C fp32.
// =====================================================================
#define GBK 32
#define ASTRB 80
#define TILEB (128*ASTRB)              // 10240
#define STAGEB (3*TILEB)               // Ah, Al, B = 30720
#define GSM (3*STAGEB)                 // 92160

template<int MODE>
__global__ __launch_bounds__(256, 2)
void mma_gemm(const half* __restrict__ Ahi, const half* __restrict__ Alo,
              const half* __restrict__ Bm,
              float* __restrict__ C, const int* __restrict__ pos, int N, int K)
{
    extern __shared__ __align__(128) char sm[];
    const u32 sbuf = smem_u32(sm);
    const int tid = threadIdx.x, wid = tid >> 5, lid = tid & 31;
    const int wm = wid & 3, wn = wid >> 2;
    const int m0 = blockIdx.x * 128;
    const int n0 = blockIdx.y * 128;
    const int nk = K / GBK;

    float acc[2][8][4];
    #pragma unroll
    for (int t = 0; t < 2; t++)
        #pragma unroll
        for (int j = 0; j < 8; j++)
            #pragma unroll
            for (int q = 0; q < 4; q++) acc[t][j][q] = 0.f;

    auto ldtile = [&](const half* g, int row0, int kc, u32 sb){
        #pragma unroll
        for (int i = 0; i < 2; i++){
            int c = tid + i*256;
            int r = c >> 2, kg = c & 3;
            cpa16(sb + r*ASTRB + kg*16, g + (size_t)(row0 + r)*K + kc + kg*8);
        }
    };
    auto ldstage = [&](int kc, int s){
        u32 sb = sbuf + s*STAGEB;
        ldtile(Ahi, m0, kc, sb);
        ldtile(Alo, m0, kc, sb + TILEB);
        ldtile(Bm,  n0, kc, sb + 2*TILEB);
        cp_commit();
    };

    const u32 a_row = (u32)(wm*32 + (lid & 15));
    const u32 a_kb  = (u32)((lid >> 4) * 16);
    const u32 b_row = (u32)(wn*64 + ((lid >> 4) & 1)*8 + (lid & 7));
    const u32 b_kb  = (u32)(((lid >> 3) & 1) * 16);

    ldstage(0, 0);
    ldstage(GBK, 1);

    for (int kt = 0; kt < nk; kt++){
        __syncthreads();                       // prior reads of stage (kt+2)%3 done
        if (kt + 2 < nk){ ldstage((kt + 2)*GBK, (kt + 2) % 3); cp_wait<2>(); }
        else if (kt + 1 < nk) cp_wait<1>();
        else cp_wait<0>();
        __syncthreads();                       // stage kt%3 visible to all

        u32 ab = sbuf + (kt % 3)*STAGEB;
        #pragma unroll
        for (int k16 = 0; k16 < 2; k16++){
            u32 kb = (u32)(k16 * 32);
            u32 ah[2][4], al[2][4];
            #pragma unroll
            for (int t = 0; t < 2; t++){
                u32 ad = ab + (a_row + t*16)*ASTRB + kb + a_kb;
                ldm_x4(ad, ah[t][0], ah[t][1], ah[t][2], ah[t][3]);
                ldm_x4(ad + TILEB, al[t][0], al[t][1], al[t][2], al[t][3]);
            }
            #pragma unroll
            for (int p = 0; p < 4; p++){
                u32 bd = ab + 2*TILEB + (b_row + p*16)*ASTRB + kb + b_kb;
                u32 h0, h1, h2, h3;
                ldm_x4(bd, h0, h1, h2, h3);
                #pragma unroll
                for (int t = 0; t < 2; t++){
                    mma16816h(acc[t][2*p],   ah[t], h0, h1);
                    mma16816h(acc[t][2*p],   al[t], h0, h1);
                    mma16816h(acc[t][2*p+1], ah[t], h2, h3);
                    mma16816h(acc[t][2*p+1], al[t], h2, h3);
                }
            }
        }
    }

    // ---------------- epilogue ----------------
    const int mrow0 = m0 + wm*32 + (lid >> 2);
    const int colw = wn*64 + 2*(lid & 3);
    if (MODE == 0){
        #pragma unroll
        for (int t = 0; t < 2; t++)
            #pragma unroll
            for (int j = 0; j < 8; j++){
                int m = mrow0 + t*16;
                int nc = n0 + colw + j*8;
                *(float2*)&C[(size_t)m*N + nc]     = make_float2(acc[t][j][0], acc[t][j][1]);
                *(float2*)&C[(size_t)(m+8)*N + nc] = make_float2(acc[t][j][2], acc[t][j][3]);
            }
    } else {
        const int head = blockIdx.y;                    // BN == DH
        const float scale = 0.08838834764831845f;
        if (head < NQH){
            const int hd = head * DH;
            #pragma unroll
            for (int t = 0; t < 2; t++){
                int m = mrow0 + t*16;
                int p0 = pos[m], p1 = pos[m + 8];
                #pragma unroll
                for (int j = 0; j < 8; j++){
                    int d = colw + j*8;
                    float invf = exp2f((float)(d >> 1) * (-13.287712379549449f / 64.f));
                    float s0, c0s, s1, c1s;
                    sincosf((float)p0 * invf, &s0, &c0s);
                    sincosf((float)p1 * invf, &s1, &c1s);
                    float x1 = acc[t][j][0], x2 = acc[t][j][1];
                    float o1 = (x1*c0s - x2*s0)*scale, o2 = (x2*c0s + x1*s0)*scale;
                    float y1 = acc[t][j][2], y2 = acc[t][j][3];
                    float u1 = (y1*c1s - y2*s1)*scale, u2 = (y2*c1s + y1*s1)*scale;
                    u32 hi, lo;
                    split2h(o1, o2, hi, lo);
                    *(u32*)(g_qh + (size_t)m*QC + hd + d) = hi;
                    *(u32*)(g_ql + (size_t)m*QC + hd + d) = lo;
                    split2h(u1, u2, hi, lo);
                    *(u32*)(g_qh + (size_t)(m+8)*QC + hd + d) = hi;
                    *(u32*)(g_ql + (size_t)(m+8)*QC + hd + d) = lo;
                }
            }
        } else if (head < NQH + NKVH){
            const int hd = (head - NQH) * DH;
            #pragma unroll
            for (int t = 0; t < 2; t++){
                int m = mrow0 + t*16;
                int p0 = pos[m], p1 = pos[m + 8];
                #pragma unroll
                for (int j = 0; j < 8; j++){
                    int d = colw + j*8;
                    float invf = exp2f((float)(d >> 1) * (-13.287712379549449f / 64.f));
                    float s0, c0s, s1, c1s;
                    sincosf((float)p0 * invf, &s0, &c0s);
                    sincosf((float)p1 * invf, &s1, &c1s);
                    float x1 = acc[t][j][0], x2 = acc[t][j][1];
                    float y1 = acc[t][j][2], y2 = acc[t][j][3];
                    *(u32*)(g_kh + (size_t)m*KVC + hd + d) =
                        packh2(x1*c0s - x2*s0, x2*c0s + x1*s0);
                    *(u32*)(g_kh + (size_t)(m+8)*KVC + hd + d) =
                        packh2(y1*c1s - y2*s1, y2*c1s + y1*s1);
                }
            }
        } else {
            const int hd = (head - NQH - NKVH) * DH;
            #pragma unroll
            for (int t = 0; t < 2; t++)
                #pragma unroll
                for (int j = 0; j < 8; j++){
                    int m = mrow0 + t*16;
                    int d = colw + j*8;
                    *(u32*)(g_vh + (size_t)m*KVC + hd + d) =
                        packh2(acc[t][j][0], acc[t][j][1]);
                    *(u32*)(g_vh + (size_t)(m+8)*KVC + hd + d) =
                        packh2(acc[t][j][2], acc[t][j][3]);
                }
        }
    }
}

// =====================================================================
// Flash attention, fp16 HMMA: QK = (Qh+Ql)K (2 MMAs), PV = P*V (1 MMA).
// Q frags register-resident. KV double-buffered. Long blocks first.
// =====================================================================
#define RSTR 272                       // 128 x 2B row + 16B pad
#define QREG (128*RSTR)                // 34816 per Q array
#define KVT  (64*RSTR)                 // 17408 per K/V array
#define KVSTAGE (2*KVT)                // kh, vh = 34816
#define ATTN_SMEM (2*QREG + 2*KVSTAGE) // 139264

__global__ __launch_bounds__(256, 1)
void attn_kernel()
{
    extern __shared__ __align__(128) char smA[];
    const u32 sb = smem_u32(smA);
    const int tid = threadIdx.x, wid = tid >> 5, lid = tid & 31;
    const int qt = gridDim.x - 1 - blockIdx.x;      // long blocks first
    const int h = blockIdx.y, b = blockIdx.z;
    const int hk = h >> 2;
    const int q0 = qt * 128;
    const int nt = qt*2 + 2;

    // Q tile load (hi + lo): 4096 x 16B
    #pragma unroll
    for (int i = 0; i < 16; i++){
        int idx = tid + i*256;
        int arr = idx >> 11, rem = idx & 2047;
        int r = rem >> 4, ch = rem & 15;
        const half* src = (arr ? g_ql : g_qh)
            + (size_t)(b*SS + q0 + r)*QC + h*DH + ch*8;
        cpa16(sb + arr*QREG + r*RSTR + ch*16, src);
    }
    auto ldkv = [&](int k0, int s){
        #pragma unroll
        for (int i = 0; i < 8; i++){
            int idx = tid + i*256;
            int arr = idx >> 10, rem = idx & 1023;
            int r = rem >> 4, ch = rem & 15;
            const half* base = arr ? g_vh : g_kh;
            cpa16(sb + 2*QREG + s*KVSTAGE + arr*KVT + r*RSTR + ch*16,
                  base + (size_t)(b*SS + k0 + r)*KVC + hk*DH + ch*8);
        }
    };
    ldkv(0, 0);
    cp_commit();                     // group: Q + KV0

    u32 qfh[8][4], qfl[8][4];
    float oacc[16][4];
    #pragma unroll
    for (int f = 0; f < 16; f++)
        #pragma unroll
        for (int q = 0; q < 4; q++) oacc[f][q] = 0.f;
    float mrow0 = -1e30f, mrow1 = -1e30f, lrow0 = 0.f, lrow1 = 0.f;

    const u32 a_base = (u32)((wid*16 + (lid & 15))*RSTR + (lid >> 4)*16);
    const u32 kb_row = (u32)((((lid >> 4) & 1)*8 + (lid & 7))*RSTR + ((lid >> 3) & 1)*16);
    const u32 vb_row = (u32)((((lid >> 3) & 1)*8 + (lid & 7))*RSTR + (lid >> 4)*16);

    for (int t = 0; t < nt; t++){
        if (t + 1 < nt){ ldkv((t + 1)*64, (t + 1) & 1); cp_commit(); cp_wait<1>(); }
        else cp_wait<0>();
        __syncthreads();

        if (t == 0){
            #pragma unroll
            for (int ks = 0; ks < 8; ks++){
                u32 ad = sb + a_base + ks*32;
                ldm_x4(ad, qfh[ks][0], qfh[ks][1], qfh[ks][2], qfh[ks][3]);
                ldm_x4(ad + QREG, qfl[ks][0], qfl[ks][1], qfl[ks][2], qfl[ks][3]);
            }
        }

        const u32 kvb = sb + 2*QREG + (t & 1)*KVSTAGE;
        float s[8][4];
        #pragma unroll
        for (int f = 0; f < 8; f++)
            #pragma unroll
            for (int q = 0; q < 4; q++) s[f][q] = 0.f;

        // S = (Qh + Ql) K^T  (fp16 x2)
        #pragma unroll
        for (int ks = 0; ks < 8; ks++){
            #pragma unroll
            for (int p = 0; p < 4; p++){
                u32 ka = kvb + p*16*RSTR + kb_row + ks*32;
                u32 h0, h1, h2, h3;
                ldm_x4(ka, h0, h1, h2, h3);
                mma16816h(s[2*p],   qfh[ks], h0, h1);
                mma16816h(s[2*p],   qfl[ks], h0, h1);
                mma16816h(s[2*p+1], qfh[ks], h2, h3);
                mma16816h(s[2*p+1], qfl[ks], h2, h3);
            }
        }

        // causal mask (tiles near diagonal)
        if (t >= nt - 2){
            int k0 = t*64;
            int qg0 = q0 + wid*16 + (lid >> 2);
            #pragma unroll
            for (int f = 0; f < 8; f++){
                int kgb = k0 + f*8 + (lid & 3)*2;
                if (kgb     > qg0) s[f][0] = -1e30f;
                if (kgb + 1 > qg0) s[f][1] = -1e30f;
                if (kgb     > qg0 + 8) s[f][2] = -1e30f;
                if (kgb + 1 > qg0 + 8) s[f][3] = -1e30f;
            }
        }

        // online softmax
        float mx0 = -1e30f, mx1 = -1e30f;
        #pragma unroll
        for (int f = 0; f < 8; f++){
            mx0 = fmaxf(mx0, fmaxf(s[f][0], s[f][1]));
            mx1 = fmaxf(mx1, fmaxf(s[f][2], s[f][3]));
        }
        mx0 = fmaxf(mx0, __shfl_xor_sync(0xffffffffu, mx0, 1));
        mx0 = fmaxf(mx0, __shfl_xor_sync(0xffffffffu, mx0, 2));
        mx1 = fmaxf(mx1, __shfl_xor_sync(0xffffffffu, mx1, 1));
        mx1 = fmaxf(mx1, __shfl_xor_sync(0xffffffffu, mx1, 2));
        float mn0 = fmaxf(mrow0, mx0), mn1 = fmaxf(mrow1, mx1);
        float al0 = __expf(mrow0 - mn0), al1 = __expf(mrow1 - mn1);
        mrow0 = mn0; mrow1 = mn1;
        float rs0 = 0.f, rs1 = 0.f;
        #pragma unroll
        for (int f = 0; f < 8; f++){
            s[f][0] = __expf(s[f][0] - mn0); rs0 += s[f][0];
            s[f][1] = __expf(s[f][1] - mn0); rs0 += s[f][1];
            s[f][2] = __expf(s[f][2] - mn1); rs1 += s[f][2];
            s[f][3] = __expf(s[f][3] - mn1); rs1 += s[f][3];
        }
        rs0 += __shfl_xor_sync(0xffffffffu, rs0, 1);
        rs0 += __shfl_xor_sync(0xffffffffu, rs0, 2);
        rs1 += __shfl_xor_sync(0xffffffffu, rs1, 1);
        rs1 += __shfl_xor_sync(0xffffffffu, rs1, 2);
        lrow0 = lrow0*al0 + rs0;
        lrow1 = lrow1*al1 + rs1;
        #pragma unroll
        for (int f = 0; f < 16; f++){
            oacc[f][0] *= al0; oacc[f][1] *= al0;
            oacc[f][2] *= al1; oacc[f][3] *= al1;
        }

        // O += P V  (P single fp16, V single fp16)
        #pragma unroll
        for (int kk = 0; kk < 4; kk++){
            u32 ph[4];
            ph[0] = packh2(s[2*kk][0],   s[2*kk][1]);
            ph[1] = packh2(s[2*kk][2],   s[2*kk][3]);
            ph[2] = packh2(s[2*kk+1][0], s[2*kk+1][1]);
            ph[3] = packh2(s[2*kk+1][2], s[2*kk+1][3]);
            #pragma unroll
            for (int p = 0; p < 8; p++){
                u32 va = kvb + KVT + kk*16*RSTR + vb_row + p*32;
                u32 h0, h1, h2, h3;
                ldm_x4t(va, h0, h1, h2, h3);
                mma16816h(oacc[2*p],   ph, h0, h1);
                mma16816h(oacc[2*p+1], ph, h2, h3);
            }
        }
        __syncthreads();
    }

    // epilogue: divide by l, split to fp16 hi/lo for O-proj A operand
    float inv0 = 1.f / lrow0, inv1 = 1.f / lrow1;
    const int row0 = q0 + wid*16 + (lid >> 2);
    const size_t tok0 = (size_t)(b*SS + row0);
    #pragma unroll
    for (int f = 0; f < 16; f++){
        int col = h*DH + f*8 + (lid & 3)*2;
        u32 hi, lo;
        split2h(oacc[f][0]*inv0, oacc[f][1]*inv0, hi, lo);
        *(u32*)(g_aA_hi + tok0*QC + col) = hi;
        *(u32*)(g_aA_lo + tok0*QC + col) = lo;
        split2h(oacc[f][2]*inv1, oacc[f][3]*inv1, hi, lo);
        *(u32*)(g_aA_hi + (tok0+8)*QC + col) = hi;
        *(u32*)(g_aA_lo + (tok0+8)*QC + col) = lo;
    }
}

// =====================================================================
extern "C" void kernel_launch(void* const* d_in, const int* in_sizes, int n_in,
                              void* d_out, int out_size)
{
    const float* hidden = (const float*)d_in[0];
    const float* wqkv   = (const float*)d_in[1];
    const float* wo     = (const float*)d_in[2];
    const int*   pos    = (const int*)d_in[3];
    float* out = (float*)d_out;

    void *p_hA_hi, *p_hA_lo, *p_wqkvT, *p_aA_hi, *p_aA_lo, *p_woT;
    cudaGetSymbolAddress(&p_hA_hi, g_hA_hi);
    cudaGetSymbolAddress(&p_hA_lo, g_hA_lo);
    cudaGetSymbolAddress(&p_wqkvT, g_wqkvT);
    cudaGetSymbolAddress(&p_aA_hi, g_aA_hi);
    cudaGetSymbolAddress(&p_aA_lo, g_aA_lo);
    cudaGetSymbolAddress(&p_woT, g_woT);

    cudaFuncSetAttribute(mma_gemm<1>, cudaFuncAttributeMaxDynamicSharedMemorySize, GSM);
    cudaFuncSetAttribute(mma_gemm<0>, cudaFuncAttributeMaxDynamicSharedMemorySize, GSM);
    cudaFuncSetAttribute(attn_kernel, cudaFuncAttributeMaxDynamicSharedMemorySize, ATTN_SMEM);

    // 1) split hidden into fp16 hi/lo
    {
        int n4 = (int)((size_t)MTOT * HH / 4);
        conv_split4<<<(n4 + 255)/256, 256>>>((const float4*)hidden,
                                             (ushort4*)p_hA_hi, (ushort4*)p_hA_lo, n4);
    }
    // 2) transpose+convert weights -> [N][K] single fp16
    convT<<<dim3(QKVN/32, HH/64), dim3(32, 8)>>>(wqkv, (half*)p_wqkvT, HH, QKVN);
    convT<<<dim3(HH/32, QC/64), dim3(32, 8)>>>(wo, (half*)p_woT, QC, HH);

    // 3) QKV projection (HMMA fp16x2) + fused RoPE + split epilogue
    mma_gemm<1><<<dim3(MTOT/128, QKVN/128), 256, GSM>>>(
        (const half*)p_hA_hi, (const half*)p_hA_lo, (const half*)p_wqkvT,
        nullptr, pos, QKVN, HH);

    // 4) causal GQA flash attention -> writes aA hi/lo
    attn_kernel<<<dim3(SS/128, NQH, NB), 256, ATTN_SMEM>>>();

    // 5) output projection (HMMA fp16x2)
    mma_gemm<0><<<dim3(MTOT/128, HH/128), 256, GSM>>>(
        (const half*)p_aA_hi, (const half*)p_aA_lo, (const half*)p_woT,
        out, nullptr, HH, QC);
}

// round 10
// speedup vs baseline: 4.4892x; 1.2025x over previous
#include <cuda_runtime.h>
#include <cuda_fp16.h>

// Problem constants
#define NB 2
#define SS 2048
#define HH 4096
#define NQH 32
#define NKVH 8
#define DH 128
#define MTOT (NB*SS)          // 4096 tokens
#define QC (NQH*DH)           // 4096
#define KVC (NKVH*DH)         // 1024
#define QKVN (QC + 2*KVC)     // 6144

typedef unsigned long long u64;
typedef unsigned int u32;

// ---------------- scratch (device globals; no allocation) ----------------
__device__ half g_hA_hi[(size_t)MTOT*HH];     // hidden fp16 hi
__device__ half g_hA_lo[(size_t)MTOT*HH];     // hidden fp16 residual
__device__ half g_wqkvT[(size_t)QKVN*HH];     // w_qkv^T single fp16
__device__ half g_aA[(size_t)MTOT*QC];        // attn out single fp16
__device__ half g_woT[(size_t)HH*QC];         // w_o^T single fp16
__device__ half g_qh[(size_t)MTOT*QC];        // Q fp16 hi (scaled+RoPE)
__device__ half g_ql[(size_t)MTOT*QC];        // Q fp16 residual
__device__ half g_kh[(size_t)MTOT*KVC];       // K single fp16 (RoPE)
__device__ half g_vh[(size_t)MTOT*KVC];       // V single fp16

// ---------------- PTX helpers ----------------
__device__ __forceinline__ u32 smem_u32(const void* p){
    u32 a; asm("{ .reg .u64 t; cvta.to.shared.u64 t, %1; cvt.u32.u64 %0, t; }" : "=r"(a) : "l"(p));
    return a;
}
__device__ __forceinline__ void cpa16(u32 s, const void* g){
    asm volatile("cp.async.cg.shared.global [%0], [%1], 16;" :: "r"(s), "l"(g));
}
__device__ __forceinline__ void cp_commit(){ asm volatile("cp.async.commit_group;"); }
template<int N> __device__ __forceinline__ void cp_wait(){
    asm volatile("cp.async.wait_group %0;" :: "n"(N));
}
__device__ __forceinline__ void ldm_x4(u32 addr, u32& r0, u32& r1, u32& r2, u32& r3){
    asm volatile("ldmatrix.sync.aligned.m8n8.x4.shared.b16 {%0,%1,%2,%3}, [%4];"
                 : "=r"(r0), "=r"(r1), "=r"(r2), "=r"(r3) : "r"(addr));
}
__device__ __forceinline__ void ldm_x4t(u32 addr, u32& r0, u32& r1, u32& r2, u32& r3){
    asm volatile("ldmatrix.sync.aligned.m8n8.x4.trans.shared.b16 {%0,%1,%2,%3}, [%4];"
                 : "=r"(r0), "=r"(r1), "=r"(r2), "=r"(r3) : "r"(addr));
}
__device__ __forceinline__ void mma16816h(float* c, const u32* a, u32 b0, u32 b1){
    asm volatile("mma.sync.aligned.m16n8k16.row.col.f32.f16.f16.f32 "
                 "{%0,%1,%2,%3}, {%4,%5,%6,%7}, {%8,%9}, {%0,%1,%2,%3};"
                 : "+f"(c[0]), "+f"(c[1]), "+f"(c[2]), "+f"(c[3])
                 : "r"(a[0]), "r"(a[1]), "r"(a[2]), "r"(a[3]), "r"(b0), "r"(b1));
}
// split two fp32 into packed fp16 hi-pair + residual-pair
__device__ __forceinline__ void split2h(float x0, float x1, u32& hi, u32& lo){
    half h0 = __float2half_rn(x0), h1 = __float2half_rn(x1);
    hi = (u32)__half_as_ushort(h0) | ((u32)__half_as_ushort(h1) << 16);
    half l0 = __float2half_rn(x0 - __half2float(h0));
    half l1 = __float2half_rn(x1 - __half2float(h1));
    lo = (u32)__half_as_ushort(l0) | ((u32)__half_as_ushort(l1) << 16);
}
__device__ __forceinline__ u32 packh2(float x0, float x1){
    half2 h = __floats2half2_rn(x0, x1);
    return *(u32*)&h;
}

// =====================================================================
// Convert kernels
// =====================================================================
__global__ void conv_split4(const float4* __restrict__ src,
                            ushort4* __restrict__ hi, ushort4* __restrict__ lo, int n4)
{
    int i = blockIdx.x * blockDim.x + threadIdx.x;
    if (i >= n4) return;
    float4 x = src[i];
    half h0 = __float2half_rn(x.x), h1 = __float2half_rn(x.y);
    half h2 = __float2half_rn(x.z), h3 = __float2half_rn(x.w);
    hi[i] = make_ushort4(__half_as_ushort(h0), __half_as_ushort(h1),
                         __half_as_ushort(h2), __half_as_ushort(h3));
    half l0 = __float2half_rn(x.x - __half2float(h0));
    half l1 = __float2half_rn(x.y - __half2float(h1));
    half l2 = __float2half_rn(x.z - __half2float(h2));
    half l3 = __float2half_rn(x.w - __half2float(h3));
    lo[i] = make_ushort4(__half_as_ushort(l0), __half_as_ushort(l1),
                         __half_as_ushort(l2), __half_as_ushort(l3));
}

// transpose + convert: src[R][C] fp32 -> dst[C][R] single fp16
__global__ void convT(const float* __restrict__ src, half* __restrict__ dstT,
                      int R, int Cc)
{
    __shared__ float t[64][33];
    int r0 = blockIdx.y * 64, c0 = blockIdx.x * 32;
    int tx = threadIdx.x, ty = threadIdx.y;  // (32,8)
    #pragma unroll
    for (int i = 0; i < 8; i++){
        int r = ty + i*8;
        t[r][tx] = src[(size_t)(r0 + r) * Cc + c0 + tx];
    }
    __syncthreads();
    #pragma unroll
    for (int i = 0; i < 4; i++){
        int cc = ty + i*8;
        half2 hv = __floats2half2_rn(t[tx*2][cc], t[tx*2+1][cc]);
        *(half2*)(dstT + (size_t)(c0 + cc) * R + r0 + tx*2) = hv;
    }
}

// =====================================================================
// HMMA fp16 GEMM: C[M,N] = (Ah [+ Al])[M,K] * B[N,K]^T.
// TERMS=2: 2-MMA split-A. TERMS=1: single-term (Ah only).
// 128x128 CTA tile, BK=32, 8 warps, 3-stage cp.async, single sync/iter.
// 2 CTAs/SM. MODE 1: epilogue -> Q hi/lo + K,V single fp16 w/ RoPE.
// MODE 0: C fp32.
// =====================================================================
#define GBK 32
#define ASTRB 80
#define TILEB (128*ASTRB)              // 10240

template<int MODE, int TERMS>
__global__ __launch_bounds__(256, 2)
void mma_gemm(const half* __restrict__ Ahi, const half* __restrict__ Alo,
              const half* __restrict__ Bm,
              float* __restrict__ C, const int* __restrict__ pos, int N, int K)
{
    constexpr u32 STAGEB = (TERMS + 1) * TILEB;
    extern __shared__ __align__(128) char sm[];
    const u32 sbuf = smem_u32(sm);
    const int tid = threadIdx.x, wid = tid >> 5, lid = tid & 31;
    const int wm = wid & 3, wn = wid >> 2;
    const int m0 = blockIdx.x * 128;
    const int n0 = blockIdx.y * 128;
    const int nk = K / GBK;

    float acc[2][8][4];
    #pragma unroll
    for (int t = 0; t < 2; t++)
        #pragma unroll
        for (int j = 0; j < 8; j++)
            #pragma unroll
            for (int q = 0; q < 4; q++) acc[t][j][q] = 0.f;

    auto ldtile = [&](const half* g, int row0, int kc, u32 sb){
        #pragma unroll
        for (int i = 0; i < 2; i++){
            int c = tid + i*256;
            int r = c >> 2, kg = c & 3;
            cpa16(sb + r*ASTRB + kg*16, g + (size_t)(row0 + r)*K + kc + kg*8);
        }
    };
    auto ldstage = [&](int kc, int s){
        u32 sb = sbuf + s*STAGEB;
        ldtile(Ahi, m0, kc, sb);
        if (TERMS == 2) ldtile(Alo, m0, kc, sb + TILEB);
        ldtile(Bm,  n0, kc, sb + TERMS*TILEB);
        cp_commit();
    };

    const u32 a_row = (u32)(wm*32 + (lid & 15));
    const u32 a_kb  = (u32)((lid >> 4) * 16);
    const u32 b_row = (u32)(wn*64 + ((lid >> 4) & 1)*8 + (lid & 7));
    const u32 b_kb  = (u32)(((lid >> 3) & 1) * 16);

    ldstage(0, 0);
    ldstage(GBK, 1);

    for (int kt = 0; kt < nk; kt++){
        if (kt + 1 < nk) cp_wait<1>(); else cp_wait<0>();
        __syncthreads();                       // stage kt visible; reads of kt-1 done
        if (kt + 2 < nk) ldstage((kt + 2)*GBK, (kt + 2) % 3);

        u32 ab = sbuf + (kt % 3)*STAGEB;
        #pragma unroll
        for (int k16 = 0; k16 < 2; k16++){
            u32 kb = (u32)(k16 * 32);
            u32 ah[2][4], al[2][4];
            #pragma unroll
            for (int t = 0; t < 2; t++){
                u32 ad = ab + (a_row + t*16)*ASTRB + kb + a_kb;
                ldm_x4(ad, ah[t][0], ah[t][1], ah[t][2], ah[t][3]);
                if (TERMS == 2)
                    ldm_x4(ad + TILEB, al[t][0], al[t][1], al[t][2], al[t][3]);
            }
            #pragma unroll
            for (int p = 0; p < 4; p++){
                u32 bd = ab + TERMS*TILEB + (b_row + p*16)*ASTRB + kb + b_kb;
                u32 h0, h1, h2, h3;
                ldm_x4(bd, h0, h1, h2, h3);
                #pragma unroll
                for (int t = 0; t < 2; t++){
                    mma16816h(acc[t][2*p],   ah[t], h0, h1);
                    if (TERMS == 2) mma16816h(acc[t][2*p], al[t], h0, h1);
                    mma16816h(acc[t][2*p+1], ah[t], h2, h3);
                    if (TERMS == 2) mma16816h(acc[t][2*p+1], al[t], h2, h3);
                }
            }
        }
    }

    // ---------------- epilogue ----------------
    const int mrow0 = m0 + wm*32 + (lid >> 2);
    const int colw = wn*64 + 2*(lid & 3);
    if (MODE == 0){
        #pragma unroll
        for (int t = 0; t < 2; t++)
            #pragma unroll
            for (int j = 0; j < 8; j++){
                int m = mrow0 + t*16;
                int nc = n0 + colw + j*8;
                *(float2*)&C[(size_t)m*N + nc]     = make_float2(acc[t][j][0], acc[t][j][1]);
                *(float2*)&C[(size_t)(m+8)*N + nc] = make_float2(acc[t][j][2], acc[t][j][3]);
            }
    } else {
        const int head = blockIdx.y;                    // BN == DH
        const float scale = 0.08838834764831845f;
        if (head < NQH){
            const int hd = head * DH;
            #pragma unroll
            for (int t = 0; t < 2; t++){
                int m = mrow0 + t*16;
                int p0 = pos[m], p1 = pos[m + 8];
                #pragma unroll
                for (int j = 0; j < 8; j++){
                    int d = colw + j*8;
                    float invf = exp2f((float)(d >> 1) * (-13.287712379549449f / 64.f));
                    float s0, c0s, s1, c1s;
                    sincosf((float)p0 * invf, &s0, &c0s);
                    sincosf((float)p1 * invf, &s1, &c1s);
                    float x1 = acc[t][j][0], x2 = acc[t][j][1];
                    float o1 = (x1*c0s - x2*s0)*scale, o2 = (x2*c0s + x1*s0)*scale;
                    float y1 = acc[t][j][2], y2 = acc[t][j][3];
                    float u1 = (y1*c1s - y2*s1)*scale, u2 = (y2*c1s + y1*s1)*scale;
                    u32 hi, lo;
                    split2h(o1, o2, hi, lo);
                    *(u32*)(g_qh + (size_t)m*QC + hd + d) = hi;
                    *(u32*)(g_ql + (size_t)m*QC + hd + d) = lo;
                    split2h(u1, u2, hi, lo);
                    *(u32*)(g_qh + (size_t)(m+8)*QC + hd + d) = hi;
                    *(u32*)(g_ql + (size_t)(m+8)*QC + hd + d) = lo;
                }
            }
        } else if (head < NQH + NKVH){
            const int hd = (head - NQH) * DH;
            #pragma unroll
            for (int t = 0; t < 2; t++){
                int m = mrow0 + t*16;
                int p0 = pos[m], p1 = pos[m + 8];
                #pragma unroll
                for (int j = 0; j < 8; j++){
                    int d = colw + j*8;
                    float invf = exp2f((float)(d >> 1) * (-13.287712379549449f / 64.f));
                    float s0, c0s, s1, c1s;
                    sincosf((float)p0 * invf, &s0, &c0s);
                    sincosf((float)p1 * invf, &s1, &c1s);
                    float x1 = acc[t][j][0], x2 = acc[t][j][1];
                    float y1 = acc[t][j][2], y2 = acc[t][j][3];
                    *(u32*)(g_kh + (size_t)m*KVC + hd + d) =
                        packh2(x1*c0s - x2*s0, x2*c0s + x1*s0);
                    *(u32*)(g_kh + (size_t)(m+8)*KVC + hd + d) =
                        packh2(y1*c1s - y2*s1, y2*c1s + y1*s1);
                }
            }
        } else {
            const int hd = (head - NQH - NKVH) * DH;
            #pragma unroll
            for (int t = 0; t < 2; t++)
                #pragma unroll
                for (int j = 0; j < 8; j++){
                    int m = mrow0 + t*16;
                    int d = colw + j*8;
                    *(u32*)(g_vh + (size_t)m*KVC + hd + d) =
                        packh2(acc[t][j][0], acc[t][j][1]);
                    *(u32*)(g_vh + (size_t)(m+8)*KVC + hd + d) =
                        packh2(acc[t][j][2], acc[t][j][3]);
                }
        }
    }
}

#define GSM2 (3*(3*TILEB))             // 92160 (TERMS=2)
#define GSM1 (3*(2*TILEB))             // 61440 (TERMS=1)

// =====================================================================
// Flash attention, fp16 HMMA: QK = (Qh+Ql)K (2 MMAs), PV = P*V (1 MMA).
// Q frags register-resident. KV double-buffered, single sync per tile.
// Long blocks first. Output written as single fp16 (O-proj is 1-term).
// =====================================================================
#define RSTR 272                       // 128 x 2B row + 16B pad
#define QREG (128*RSTR)                // 34816 per Q array
#define KVT  (64*RSTR)                 // 17408 per K/V array
#define KVSTAGE (2*KVT)                // kh, vh = 34816
#define ATTN_SMEM (2*QREG + 2*KVSTAGE) // 139264

__global__ __launch_bounds__(256, 1)
void attn_kernel()
{
    extern __shared__ __align__(128) char smA[];
    const u32 sb = smem_u32(smA);
    const int tid = threadIdx.x, wid = tid >> 5, lid = tid & 31;
    const int qt = gridDim.x - 1 - blockIdx.x;      // long blocks first
    const int h = blockIdx.y, b = blockIdx.z;
    const int hk = h >> 2;
    const int q0 = qt * 128;
    const int nt = qt*2 + 2;

    auto ldkv = [&](int k0, int s){
        #pragma unroll
        for (int i = 0; i < 8; i++){
            int idx = tid + i*256;
            int arr = idx >> 10, rem = idx & 1023;
            int r = rem >> 4, ch = rem & 15;
            const half* base = arr ? g_vh : g_kh;
            cpa16(sb + 2*QREG + s*KVSTAGE + arr*KVT + r*RSTR + ch*16,
                  base + (size_t)(b*SS + k0 + r)*KVC + hk*DH + ch*8);
        }
    };

    // prologue: Q (hi+lo) + KV0 in one group
    #pragma unroll
    for (int i = 0; i < 16; i++){
        int idx = tid + i*256;
        int arr = idx >> 11, rem = idx & 2047;
        int r = rem >> 4, ch = rem & 15;
        const half* src = (arr ? g_ql : g_qh)
            + (size_t)(b*SS + q0 + r)*QC + h*DH + ch*8;
        cpa16(sb + arr*QREG + r*RSTR + ch*16, src);
    }
    ldkv(0, 0);
    cp_commit();

    u32 qfh[8][4], qfl[8][4];
    float oacc[16][4];
    #pragma unroll
    for (int f = 0; f < 16; f++)
        #pragma unroll
        for (int q = 0; q < 4; q++) oacc[f][q] = 0.f;
    float mrow0 = -1e30f, mrow1 = -1e30f, lrow0 = 0.f, lrow1 = 0.f;

    const u32 a_base = (u32)((wid*16 + (lid & 15))*RSTR + (lid >> 4)*16);
    const u32 kb_row = (u32)((((lid >> 4) & 1)*8 + (lid & 7))*RSTR + ((lid >> 3) & 1)*16);
    const u32 vb_row = (u32)((((lid >> 3) & 1)*8 + (lid & 7))*RSTR + (lid >> 4)*16);

    for (int t = 0; t < nt; t++){
        cp_wait<0>();                  // stage t (and Q at t=0) complete
        __syncthreads();               // visible; reads of stage t-1 done
        if (t + 1 < nt){ ldkv((t + 1)*64, (t + 1) & 1); cp_commit(); }

        if (t == 0){
            #pragma unroll
            for (int ks = 0; ks < 8; ks++){
                u32 ad = sb + a_base + ks*32;
                ldm_x4(ad, qfh[ks][0], qfh[ks][1], qfh[ks][2], qfh[ks][3]);
                ldm_x4(ad + QREG, qfl[ks][0], qfl[ks][1], qfl[ks][2], qfl[ks][3]);
            }
        }

        const u32 kvb = sb + 2*QREG + (t & 1)*KVSTAGE;
        float s[8][4];
        #pragma unroll
        for (int f = 0; f < 8; f++)
            #pragma unroll
            for (int q = 0; q < 4; q++) s[f][q] = 0.f;

        // S = (Qh + Ql) K^T  (fp16 x2)
        #pragma unroll
        for (int ks = 0; ks < 8; ks++){
            #pragma unroll
            for (int p = 0; p < 4; p++){
                u32 ka = kvb + p*16*RSTR + kb_row + ks*32;
                u32 h0, h1, h2, h3;
                ldm_x4(ka, h0, h1, h2, h3);
                mma16816h(s[2*p],   qfh[ks], h0, h1);
                mma16816h(s[2*p],   qfl[ks], h0, h1);
                mma16816h(s[2*p+1], qfh[ks], h2, h3);
                mma16816h(s[2*p+1], qfl[ks], h2, h3);
            }
        }

        // causal mask (tiles near diagonal)
        if (t >= nt - 2){
            int k0 = t*64;
            int qg0 = q0 + wid*16 + (lid >> 2);
            #pragma unroll
            for (int f = 0; f < 8; f++){
                int kgb = k0 + f*8 + (lid & 3)*2;
                if (kgb     > qg0) s[f][0] = -1e30f;
                if (kgb + 1 > qg0) s[f][1] = -1e30f;
                if (kgb     > qg0 + 8) s[f][2] = -1e30f;
                if (kgb + 1 > qg0 + 8) s[f][3] = -1e30f;
            }
        }

        // online softmax
        float mx0 = -1e30f, mx1 = -1e30f;
        #pragma unroll
        for (int f = 0; f < 8; f++){
            mx0 = fmaxf(mx0, fmaxf(s[f][0], s[f][1]));
            mx1 = fmaxf(mx1, fmaxf(s[f][2], s[f][3]));
        }
        mx0 = fmaxf(mx0, __shfl_xor_sync(0xffffffffu, mx0, 1));
        mx0 = fmaxf(mx0, __shfl_xor_sync(0xffffffffu, mx0, 2));
        mx1 = fmaxf(mx1, __shfl_xor_sync(0xffffffffu, mx1, 1));
        mx1 = fmaxf(mx1, __shfl_xor_sync(0xffffffffu, mx1, 2));
        float mn0 = fmaxf(mrow0, mx0), mn1 = fmaxf(mrow1, mx1);
        float al0 = __expf(mrow0 - mn0), al1 = __expf(mrow1 - mn1);
        mrow0 = mn0; mrow1 = mn1;
        float rs0 = 0.f, rs1 = 0.f;
        #pragma unroll
        for (int f = 0; f < 8; f++){
            s[f][0] = __expf(s[f][0] - mn0); rs0 += s[f][0];
            s[f][1] = __expf(s[f][1] - mn0); rs0 += s[f][1];
            s[f][2] = __expf(s[f][2] - mn1); rs1 += s[f][2];
            s[f][3] = __expf(s[f][3] - mn1); rs1 += s[f][3];
        }
        rs0 += __shfl_xor_sync(0xffffffffu, rs0, 1);
        rs0 += __shfl_xor_sync(0xffffffffu, rs0, 2);
        rs1 += __shfl_xor_sync(0xffffffffu, rs1, 1);
        rs1 += __shfl_xor_sync(0xffffffffu, rs1, 2);
        lrow0 = lrow0*al0 + rs0;
        lrow1 = lrow1*al1 + rs1;
        #pragma unroll
        for (int f = 0; f < 16; f++){
            oacc[f][0] *= al0; oacc[f][1] *= al0;
            oacc[f][2] *= al1; oacc[f][3] *= al1;
        }

        // O += P V  (P single fp16, V single fp16)
        #pragma unroll
        for (int kk = 0; kk < 4; kk++){
            u32 ph[4];
            ph[0] = packh2(s[2*kk][0],   s[2*kk][1]);
            ph[1] = packh2(s[2*kk][2],   s[2*kk][3]);
            ph[2] = packh2(s[2*kk+1][0], s[2*kk+1][1]);
            ph[3] = packh2(s[2*kk+1][2], s[2*kk+1][3]);
            #pragma unroll
            for (int p = 0; p < 8; p++){
                u32 va = kvb + KVT + kk*16*RSTR + vb_row + p*32;
                u32 h0, h1, h2, h3;
                ldm_x4t(va, h0, h1, h2, h3);
                mma16816h(oacc[2*p],   ph, h0, h1);
                mma16816h(oacc[2*p+1], ph, h2, h3);
            }
        }
    }

    // epilogue: divide by l, write single fp16 (O-proj A operand)
    float inv0 = 1.f / lrow0, inv1 = 1.f / lrow1;
    const int row0 = q0 + wid*16 + (lid >> 2);
    const size_t tok0 = (size_t)(b*SS + row0);
    #pragma unroll
    for (int f = 0; f < 16; f++){
        int col = h*DH + f*8 + (lid & 3)*2;
        *(u32*)(g_aA + tok0*QC + col)     = packh2(oacc[f][0]*inv0, oacc[f][1]*inv0);
        *(u32*)(g_aA + (tok0+8)*QC + col) = packh2(oacc[f][2]*inv1, oacc[f][3]*inv1);
    }
}

// =====================================================================
extern "C" void kernel_launch(void* const* d_in, const int* in_sizes, int n_in,
                              void* d_out, int out_size)
{
    const float* hidden = (const float*)d_in[0];
    const float* wqkv   = (const float*)d_in[1];
    const float* wo     = (const float*)d_in[2];
    const int*   pos    = (const int*)d_in[3];
    float* out = (float*)d_out;

    void *p_hA_hi, *p_hA_lo, *p_wqkvT, *p_aA, *p_woT;
    cudaGetSymbolAddress(&p_hA_hi, g_hA_hi);
    cudaGetSymbolAddress(&p_hA_lo, g_hA_lo);
    cudaGetSymbolAddress(&p_wqkvT, g_wqkvT);
    cudaGetSymbolAddress(&p_aA, g_aA);
    cudaGetSymbolAddress(&p_woT, g_woT);

    cudaFuncSetAttribute((mma_gemm<1,2>), cudaFuncAttributeMaxDynamicSharedMemorySize, GSM2);
    cudaFuncSetAttribute((mma_gemm<0,1>), cudaFuncAttributeMaxDynamicSharedMemorySize, GSM1);
    cudaFuncSetAttribute(attn_kernel, cudaFuncAttributeMaxDynamicSharedMemorySize, ATTN_SMEM);

    // 1) split hidden into fp16 hi/lo
    {
        int n4 = (int)((size_t)MTOT * HH / 4);
        conv_split4<<<(n4 + 255)/256, 256>>>((const float4*)hidden,
                                             (ushort4*)p_hA_hi, (ushort4*)p_hA_lo, n4);
    }
    // 2) transpose+convert weights -> [N][K] single fp16
    convT<<<dim3(QKVN/32, HH/64), dim3(32, 8)>>>(wqkv, (half*)p_wqkvT, HH, QKVN);
    convT<<<dim3(HH/32, QC/64), dim3(32, 8)>>>(wo, (half*)p_woT, QC, HH);

    // 3) QKV projection (fp16, 2-term) + fused RoPE + split epilogue
    mma_gemm<1,2><<<dim3(MTOT/128, QKVN/128), 256, GSM2>>>(
        (const half*)p_hA_hi, (const half*)p_hA_lo, (const half*)p_wqkvT,
        nullptr, pos, QKVN, HH);

    // 4) causal GQA flash attention -> writes aA single fp16
    attn_kernel<<<dim3(SS/128, NQH, NB), 256, ATTN_SMEM>>>();

    // 5) output projection (fp16, 1-term)
    mma_gemm<0,1><<<dim3(MTOT/128, HH/128), 256, GSM1>>>(
        (const half*)p_aA, nullptr, (const half*)p_woT,
        out, nullptr, HH, QC);
}

// round 11
// speedup vs baseline: 6.1476x; 1.3694x over previous
#include <cuda_runtime.h>
#include <cuda_fp16.h>

// Problem constants
#define NB 2
#define SS 2048
#define HH 4096
#define NQH 32
#define NKVH 8
#define DH 128
#define MTOT (NB*SS)          // 4096 tokens
#define QC (NQH*DH)           // 4096
#define KVC (NKVH*DH)         // 1024
#define QKVN (QC + 2*KVC)     // 6144

typedef unsigned long long u64;
typedef unsigned int u32;

// ---------------- scratch (device globals; no allocation) ----------------
__device__ half g_hA[(size_t)MTOT*HH];        // hidden single fp16
__device__ half g_wqkvT[(size_t)QKVN*HH];     // w_qkv^T single fp16
__device__ half g_aA[(size_t)MTOT*QC];        // attn out single fp16
__device__ half g_woT[(size_t)HH*QC];         // w_o^T single fp16
__device__ half g_qh[(size_t)MTOT*QC];        // Q fp16 hi (scaled+RoPE)
__device__ half g_ql[(size_t)MTOT*QC];        // Q fp16 residual
__device__ half g_kh[(size_t)MTOT*KVC];       // K single fp16 (RoPE)
__device__ half g_vh[(size_t)MTOT*KVC];       // V single fp16

// ---------------- PTX helpers ----------------
__device__ __forceinline__ u32 smem_u32(const void* p){
    u32 a; asm("{ .reg .u64 t; cvta.to.shared.u64 t, %1; cvt.u32.u64 %0, t; }" : "=r"(a) : "l"(p));
    return a;
}
__device__ __forceinline__ void cpa16(u32 s, const void* g){
    asm volatile("cp.async.cg.shared.global [%0], [%1], 16;" :: "r"(s), "l"(g));
}
__device__ __forceinline__ void cp_commit(){ asm volatile("cp.async.commit_group;"); }
template<int N> __device__ __forceinline__ void cp_wait(){
    asm volatile("cp.async.wait_group %0;" :: "n"(N));
}
__device__ __forceinline__ void ldm_x4(u32 addr, u32& r0, u32& r1, u32& r2, u32& r3){
    asm volatile("ldmatrix.sync.aligned.m8n8.x4.shared.b16 {%0,%1,%2,%3}, [%4];"
                 : "=r"(r0), "=r"(r1), "=r"(r2), "=r"(r3) : "r"(addr));
}
__device__ __forceinline__ void ldm_x4t(u32 addr, u32& r0, u32& r1, u32& r2, u32& r3){
    asm volatile("ldmatrix.sync.aligned.m8n8.x4.trans.shared.b16 {%0,%1,%2,%3}, [%4];"
                 : "=r"(r0), "=r"(r1), "=r"(r2), "=r"(r3) : "r"(addr));
}
__device__ __forceinline__ void mma16816h(float* c, const u32* a, u32 b0, u32 b1){
    asm volatile("mma.sync.aligned.m16n8k16.row.col.f32.f16.f16.f32 "
                 "{%0,%1,%2,%3}, {%4,%5,%6,%7}, {%8,%9}, {%0,%1,%2,%3};"
                 : "+f"(c[0]), "+f"(c[1]), "+f"(c[2]), "+f"(c[3])
                 : "r"(a[0]), "r"(a[1]), "r"(a[2]), "r"(a[3]), "r"(b0), "r"(b1));
}
// split two fp32 into packed fp16 hi-pair + residual-pair
__device__ __forceinline__ void split2h(float x0, float x1, u32& hi, u32& lo){
    half h0 = __float2half_rn(x0), h1 = __float2half_rn(x1);
    hi = (u32)__half_as_ushort(h0) | ((u32)__half_as_ushort(h1) << 16);
    half l0 = __float2half_rn(x0 - __half2float(h0));
    half l1 = __float2half_rn(x1 - __half2float(h1));
    lo = (u32)__half_as_ushort(l0) | ((u32)__half_as_ushort(l1) << 16);
}
__device__ __forceinline__ u32 packh2(float x0, float x1){
    half2 h = __floats2half2_rn(x0, x1);
    return *(u32*)&h;
}

// =====================================================================
// Convert kernels
// =====================================================================
__global__ void conv_h4(const float4* __restrict__ src, ushort4* __restrict__ dst, int n4)
{
    int i = blockIdx.x * blockDim.x + threadIdx.x;
    if (i >= n4) return;
    float4 x = src[i];
    dst[i] = make_ushort4(__half_as_ushort(__float2half_rn(x.x)),
                          __half_as_ushort(__float2half_rn(x.y)),
                          __half_as_ushort(__float2half_rn(x.z)),
                          __half_as_ushort(__float2half_rn(x.w)));
}

// transpose + convert: src[R][C] fp32 -> dst[C][R] single fp16
__global__ void convT(const float* __restrict__ src, half* __restrict__ dstT,
                      int R, int Cc)
{
    __shared__ float t[64][33];
    int r0 = blockIdx.y * 64, c0 = blockIdx.x * 32;
    int tx = threadIdx.x, ty = threadIdx.y;  // (32,8)
    #pragma unroll
    for (int i = 0; i < 8; i++){
        int r = ty + i*8;
        t[r][tx] = src[(size_t)(r0 + r) * Cc + c0 + tx];
    }
    __syncthreads();
    #pragma unroll
    for (int i = 0; i < 4; i++){
        int cc = ty + i*8;
        half2 hv = __floats2half2_rn(t[tx*2][cc], t[tx*2+1][cc]);
        *(half2*)(dstT + (size_t)(c0 + cc) * R + r0 + tx*2) = hv;
    }
}

// =====================================================================
// HMMA fp16 GEMM: C[M,N] = A[M,K] * B[N,K]^T  (single-term fp16).
// 128x128 CTA tile, BK=32, 8 warps, 3-stage cp.async, single sync/iter.
// 2 CTAs/SM. MODE 1: epilogue -> Q hi/lo + K,V single fp16 w/ RoPE.
// MODE 0: C fp32.
// =====================================================================
#define GBK 32
#define ASTRB 80
#define TILEB (128*ASTRB)              // 10240
#define STAGEB (2*TILEB)               // A, B = 20480
#define GSM (3*STAGEB)                 // 61440

template<int MODE>
__global__ __launch_bounds__(256, 2)
void mma_gemm(const half* __restrict__ Am, const half* __restrict__ Bm,
              float* __restrict__ C, const int* __restrict__ pos, int N, int K)
{
    extern __shared__ __align__(128) char sm[];
    const u32 sbuf = smem_u32(sm);
    const int tid = threadIdx.x, wid = tid >> 5, lid = tid & 31;
    const int wm = wid & 3, wn = wid >> 2;
    const int m0 = blockIdx.x * 128;
    const int n0 = blockIdx.y * 128;
    const int nk = K / GBK;

    float acc[2][8][4];
    #pragma unroll
    for (int t = 0; t < 2; t++)
        #pragma unroll
        for (int j = 0; j < 8; j++)
            #pragma unroll
            for (int q = 0; q < 4; q++) acc[t][j][q] = 0.f;

    auto ldtile = [&](const half* g, int row0, int kc, u32 sb){
        #pragma unroll
        for (int i = 0; i < 2; i++){
            int c = tid + i*256;
            int r = c >> 2, kg = c & 3;
            cpa16(sb + r*ASTRB + kg*16, g + (size_t)(row0 + r)*K + kc + kg*8);
        }
    };
    auto ldstage = [&](int kc, int s){
        u32 sb = sbuf + s*STAGEB;
        ldtile(Am, m0, kc, sb);
        ldtile(Bm, n0, kc, sb + TILEB);
        cp_commit();
    };

    const u32 a_row = (u32)(wm*32 + (lid & 15));
    const u32 a_kb  = (u32)((lid >> 4) * 16);
    const u32 b_row = (u32)(wn*64 + ((lid >> 4) & 1)*8 + (lid & 7));
    const u32 b_kb  = (u32)(((lid >> 3) & 1) * 16);

    ldstage(0, 0);
    ldstage(GBK, 1);

    for (int kt = 0; kt < nk; kt++){
        if (kt + 1 < nk) cp_wait<1>(); else cp_wait<0>();
        __syncthreads();                       // stage kt visible; reads of kt-1 done
        if (kt + 2 < nk) ldstage((kt + 2)*GBK, (kt + 2) % 3);

        u32 ab = sbuf + (kt % 3)*STAGEB;
        #pragma unroll
        for (int k16 = 0; k16 < 2; k16++){
            u32 kb = (u32)(k16 * 32);
            u32 ah[2][4];
            #pragma unroll
            for (int t = 0; t < 2; t++){
                u32 ad = ab + (a_row + t*16)*ASTRB + kb + a_kb;
                ldm_x4(ad, ah[t][0], ah[t][1], ah[t][2], ah[t][3]);
            }
            #pragma unroll
            for (int p = 0; p < 4; p++){
                u32 bd = ab + TILEB + (b_row + p*16)*ASTRB + kb + b_kb;
                u32 h0, h1, h2, h3;
                ldm_x4(bd, h0, h1, h2, h3);
                #pragma unroll
                for (int t = 0; t < 2; t++){
                    mma16816h(acc[t][2*p],   ah[t], h0, h1);
                    mma16816h(acc[t][2*p+1], ah[t], h2, h3);
                }
            }
        }
    }

    // ---------------- epilogue ----------------
    const int mrow0 = m0 + wm*32 + (lid >> 2);
    const int colw = wn*64 + 2*(lid & 3);
    if (MODE == 0){
        #pragma unroll
        for (int t = 0; t < 2; t++)
            #pragma unroll
            for (int j = 0; j < 8; j++){
                int m = mrow0 + t*16;
                int nc = n0 + colw + j*8;
                *(float2*)&C[(size_t)m*N + nc]     = make_float2(acc[t][j][0], acc[t][j][1]);
                *(float2*)&C[(size_t)(m+8)*N + nc] = make_float2(acc[t][j][2], acc[t][j][3]);
            }
    } else {
        const int head = blockIdx.y;                    // BN == DH
        const float scale = 0.08838834764831845f;
        if (head < NQH){
            const int hd = head * DH;
            #pragma unroll
            for (int t = 0; t < 2; t++){
                int m = mrow0 + t*16;
                int p0 = pos[m], p1 = pos[m + 8];
                #pragma unroll
                for (int j = 0; j < 8; j++){
                    int d = colw + j*8;
                    float invf = exp2f((float)(d >> 1) * (-13.287712379549449f / 64.f));
                    float s0, c0s, s1, c1s;
                    sincosf((float)p0 * invf, &s0, &c0s);
                    sincosf((float)p1 * invf, &s1, &c1s);
                    float x1 = acc[t][j][0], x2 = acc[t][j][1];
                    float o1 = (x1*c0s - x2*s0)*scale, o2 = (x2*c0s + x1*s0)*scale;
                    float y1 = acc[t][j][2], y2 = acc[t][j][3];
                    float u1 = (y1*c1s - y2*s1)*scale, u2 = (y2*c1s + y1*s1)*scale;
                    u32 hi, lo;
                    split2h(o1, o2, hi, lo);
                    *(u32*)(g_qh + (size_t)m*QC + hd + d) = hi;
                    *(u32*)(g_ql + (size_t)m*QC + hd + d) = lo;
                    split2h(u1, u2, hi, lo);
                    *(u32*)(g_qh + (size_t)(m+8)*QC + hd + d) = hi;
                    *(u32*)(g_ql + (size_t)(m+8)*QC + hd + d) = lo;
                }
            }
        } else if (head < NQH + NKVH){
            const int hd = (head - NQH) * DH;
            #pragma unroll
            for (int t = 0; t < 2; t++){
                int m = mrow0 + t*16;
                int p0 = pos[m], p1 = pos[m + 8];
                #pragma unroll
                for (int j = 0; j < 8; j++){
                    int d = colw + j*8;
                    float invf = exp2f((float)(d >> 1) * (-13.287712379549449f / 64.f));
                    float s0, c0s, s1, c1s;
                    sincosf((float)p0 * invf, &s0, &c0s);
                    sincosf((float)p1 * invf, &s1, &c1s);
                    float x1 = acc[t][j][0], x2 = acc[t][j][1];
                    float y1 = acc[t][j][2], y2 = acc[t][j][3];
                    *(u32*)(g_kh + (size_t)m*KVC + hd + d) =
                        packh2(x1*c0s - x2*s0, x2*c0s + x1*s0);
                    *(u32*)(g_kh + (size_t)(m+8)*KVC + hd + d) =
                        packh2(y1*c1s - y2*s1, y2*c1s + y1*s1);
                }
            }
        } else {
            const int hd = (head - NQH - NKVH) * DH;
            #pragma unroll
            for (int t = 0; t < 2; t++)
                #pragma unroll
                for (int j = 0; j < 8; j++){
                    int m = mrow0 + t*16;
                    int d = colw + j*8;
                    *(u32*)(g_vh + (size_t)m*KVC + hd + d) =
                        packh2(acc[t][j][0], acc[t][j][1]);
                    *(u32*)(g_vh + (size_t)(m+8)*KVC + hd + d) =
                        packh2(acc[t][j][2], acc[t][j][3]);
                }
        }
    }
}

// =====================================================================
// Flash attention, fp16 HMMA: QK = (Qh+Ql)K (2 MMAs), PV = P*V (1 MMA).
// Q frags register-resident. KV double-buffered, single sync per tile.
// Long blocks first. Output written as single fp16 (O-proj is 1-term).
// =====================================================================
#define RSTR 272                       // 128 x 2B row + 16B pad
#define QREG (128*RSTR)                // 34816 per Q array
#define KVT  (64*RSTR)                 // 17408 per K/V array
#define KVSTAGE (2*KVT)                // kh, vh = 34816
#define ATTN_SMEM (2*QREG + 2*KVSTAGE) // 139264

__global__ __launch_bounds__(256, 1)
void attn_kernel()
{
    extern __shared__ __align__(128) char smA[];
    const u32 sb = smem_u32(smA);
    const int tid = threadIdx.x, wid = tid >> 5, lid = tid & 31;
    const int qt = gridDim.x - 1 - blockIdx.x;      // long blocks first
    const int h = blockIdx.y, b = blockIdx.z;
    const int hk = h >> 2;
    const int q0 = qt * 128;
    const int nt = qt*2 + 2;

    auto ldkv = [&](int k0, int s){
        #pragma unroll
        for (int i = 0; i < 8; i++){
            int idx = tid + i*256;
            int arr = idx >> 10, rem = idx & 1023;
            int r = rem >> 4, ch = rem & 15;
            const half* base = arr ? g_vh : g_kh;
            cpa16(sb + 2*QREG + s*KVSTAGE + arr*KVT + r*RSTR + ch*16,
                  base + (size_t)(b*SS + k0 + r)*KVC + hk*DH + ch*8);
        }
    };

    // prologue: Q (hi+lo) + KV0 in one group
    #pragma unroll
    for (int i = 0; i < 16; i++){
        int idx = tid + i*256;
        int arr = idx >> 11, rem = idx & 2047;
        int r = rem >> 4, ch = rem & 15;
        const half* src = (arr ? g_ql : g_qh)
            + (size_t)(b*SS + q0 + r)*QC + h*DH + ch*8;
        cpa16(sb + arr*QREG + r*RSTR + ch*16, src);
    }
    ldkv(0, 0);
    cp_commit();

    u32 qfh[8][4], qfl[8][4];
    float oacc[16][4];
    #pragma unroll
    for (int f = 0; f < 16; f++)
        #pragma unroll
        for (int q = 0; q < 4; q++) oacc[f][q] = 0.f;
    float mrow0 = -1e30f, mrow1 = -1e30f, lrow0 = 0.f, lrow1 = 0.f;

    const u32 a_base = (u32)((wid*16 + (lid & 15))*RSTR + (lid >> 4)*16);
    const u32 kb_row = (u32)((((lid >> 4) & 1)*8 + (lid & 7))*RSTR + ((lid >> 3) & 1)*16);
    const u32 vb_row = (u32)((((lid >> 3) & 1)*8 + (lid & 7))*RSTR + (lid >> 4)*16);

    for (int t = 0; t < nt; t++){
        cp_wait<0>();                  // stage t (and Q at t=0) complete
        __syncthreads();               // visible; reads of stage t-1 done
        if (t + 1 < nt){ ldkv((t + 1)*64, (t + 1) & 1); cp_commit(); }

        if (t == 0){
            #pragma unroll
            for (int ks = 0; ks < 8; ks++){
                u32 ad = sb + a_base + ks*32;
                ldm_x4(ad, qfh[ks][0], qfh[ks][1], qfh[ks][2], qfh[ks][3]);
                ldm_x4(ad + QREG, qfl[ks][0], qfl[ks][1], qfl[ks][2], qfl[ks][3]);
            }
        }

        const u32 kvb = sb + 2*QREG + (t & 1)*KVSTAGE;
        float s[8][4];
        #pragma unroll
        for (int f = 0; f < 8; f++)
            #pragma unroll
            for (int q = 0; q < 4; q++) s[f][q] = 0.f;

        // S = (Qh + Ql) K^T  (fp16 x2)
        #pragma unroll
        for (int ks = 0; ks < 8; ks++){
            #pragma unroll
            for (int p = 0; p < 4; p++){
                u32 ka = kvb + p*16*RSTR + kb_row + ks*32;
                u32 h0, h1, h2, h3;
                ldm_x4(ka, h0, h1, h2, h3);
                mma16816h(s[2*p],   qfh[ks], h0, h1);
                mma16816h(s[2*p],   qfl[ks], h0, h1);
                mma16816h(s[2*p+1], qfh[ks], h2, h3);
                mma16816h(s[2*p+1], qfl[ks], h2, h3);
            }
        }

        // causal mask (tiles near diagonal)
        if (t >= nt - 2){
            int k0 = t*64;
            int qg0 = q0 + wid*16 + (lid >> 2);
            #pragma unroll
            for (int f = 0; f < 8; f++){
                int kgb = k0 + f*8 + (lid & 3)*2;
                if (kgb     > qg0) s[f][0] = -1e30f;
                if (kgb + 1 > qg0) s[f][1] = -1e30f;
                if (kgb     > qg0 + 8) s[f][2] = -1e30f;
                if (kgb + 1 > qg0 + 8) s[f][3] = -1e30f;
            }
        }

        // online softmax
        float mx0 = -1e30f, mx1 = -1e30f;
        #pragma unroll
        for (int f = 0; f < 8; f++){
            mx0 = fmaxf(mx0, fmaxf(s[f][0], s[f][1]));
            mx1 = fmaxf(mx1, fmaxf(s[f][2], s[f][3]));
        }
        mx0 = fmaxf(mx0, __shfl_xor_sync(0xffffffffu, mx0, 1));
        mx0 = fmaxf(mx0, __shfl_xor_sync(0xffffffffu, mx0, 2));
        mx1 = fmaxf(mx1, __shfl_xor_sync(0xffffffffu, mx1, 1));
        mx1 = fmaxf(mx1, __shfl_xor_sync(0xffffffffu, mx1, 2));
        float mn0 = fmaxf(mrow0, mx0), mn1 = fmaxf(mrow1, mx1);
        float al0 = __expf(mrow0 - mn0), al1 = __expf(mrow1 - mn1);
        mrow0 = mn0; mrow1 = mn1;
        float rs0 = 0.f, rs1 = 0.f;
        #pragma unroll
        for (int f = 0; f < 8; f++){
            s[f][0] = __expf(s[f][0] - mn0); rs0 += s[f][0];
            s[f][1] = __expf(s[f][1] - mn0); rs0 += s[f][1];
            s[f][2] = __expf(s[f][2] - mn1); rs1 += s[f][2];
            s[f][3] = __expf(s[f][3] - mn1); rs1 += s[f][3];
        }
        rs0 += __shfl_xor_sync(0xffffffffu, rs0, 1);
        rs0 += __shfl_xor_sync(0xffffffffu, rs0, 2);
        rs1 += __shfl_xor_sync(0xffffffffu, rs1, 1);
        rs1 += __shfl_xor_sync(0xffffffffu, rs1, 2);
        lrow0 = lrow0*al0 + rs0;
        lrow1 = lrow1*al1 + rs1;
        #pragma unroll
        for (int f = 0; f < 16; f++){
            oacc[f][0] *= al0; oacc[f][1] *= al0;
            oacc[f][2] *= al1; oacc[f][3] *= al1;
        }

        // O += P V  (P single fp16, V single fp16)
        #pragma unroll
        for (int kk = 0; kk < 4; kk++){
            u32 ph[4];
            ph[0] = packh2(s[2*kk][0],   s[2*kk][1]);
            ph[1] = packh2(s[2*kk][2],   s[2*kk][3]);
            ph[2] = packh2(s[2*kk+1][0], s[2*kk+1][1]);
            ph[3] = packh2(s[2*kk+1][2], s[2*kk+1][3]);
            #pragma unroll
            for (int p = 0; p < 8; p++){
                u32 va = kvb + KVT + kk*16*RSTR + vb_row + p*32;
                u32 h0, h1, h2, h3;
                ldm_x4t(va, h0, h1, h2, h3);
                mma16816h(oacc[2*p],   ph, h0, h1);
                mma16816h(oacc[2*p+1], ph, h2, h3);
            }
        }
    }

    // epilogue: divide by l, write single fp16 (O-proj A operand)
    float inv0 = 1.f / lrow0, inv1 = 1.f / lrow1;
    const int row0 = q0 + wid*16 + (lid >> 2);
    const size_t tok0 = (size_t)(b*SS + row0);
    #pragma unroll
    for (int f = 0; f < 16; f++){
        int col = h*DH + f*8 + (lid & 3)*2;
        *(u32*)(g_aA + tok0*QC + col)     = packh2(oacc[f][0]*inv0, oacc[f][1]*inv0);
        *(u32*)(g_aA + (tok0+8)*QC + col) = packh2(oacc[f][2]*inv1, oacc[f][3]*inv1);
    }
}

// =====================================================================
extern "C" void kernel_launch(void* const* d_in, const int* in_sizes, int n_in,
                              void* d_out, int out_size)
{
    const float* hidden = (const float*)d_in[0];
    const float* wqkv   = (const float*)d_in[1];
    const float* wo     = (const float*)d_in[2];
    const int*   pos    = (const int*)d_in[3];
    float* out = (float*)d_out;

    void *p_hA, *p_wqkvT, *p_aA, *p_woT;
    cudaGetSymbolAddress(&p_hA, g_hA);
    cudaGetSymbolAddress(&p_wqkvT, g_wqkvT);
    cudaGetSymbolAddress(&p_aA, g_aA);
    cudaGetSymbolAddress(&p_woT, g_woT);

    cudaFuncSetAttribute(mma_gemm<1>, cudaFuncAttributeMaxDynamicSharedMemorySize, GSM);
    cudaFuncSetAttribute(mma_gemm<0>, cudaFuncAttributeMaxDynamicSharedMemorySize, GSM);
    cudaFuncSetAttribute(attn_kernel, cudaFuncAttributeMaxDynamicSharedMemorySize, ATTN_SMEM);

    // 1) convert hidden to single fp16
    {
        int n4 = (int)((size_t)MTOT * HH / 4);
        conv_h4<<<(n4 + 255)/256, 256>>>((const float4*)hidden, (ushort4*)p_hA, n4);
    }
    // 2) transpose+convert weights -> [N][K] single fp16
    convT<<<dim3(QKVN/32, HH/64), dim3(32, 8)>>>(wqkv, (half*)p_wqkvT, HH, QKVN);
    convT<<<dim3(HH/32, QC/64), dim3(32, 8)>>>(wo, (half*)p_woT, QC, HH);

    // 3) QKV projection (fp16, 1-term) + fused RoPE + split epilogue
    mma_gemm<1><<<dim3(MTOT/128, QKVN/128), 256, GSM>>>(
        (const half*)p_hA, (const half*)p_wqkvT, nullptr, pos, QKVN, HH);

    // 4) causal GQA flash attention -> writes aA single fp16
    attn_kernel<<<dim3(SS/128, NQH, NB), 256, ATTN_SMEM>>>();

    // 5) output projection (fp16, 1-term)
    mma_gemm<0><<<dim3(MTOT/128, HH/128), 256, GSM>>>(
        (const half*)p_aA, (const half*)p_woT, out, nullptr, HH, QC);
}

// round 13
// speedup vs baseline: 6.6572x; 1.0829x over previous
#include <cuda_runtime.h>
#include <cuda_fp16.h>

// Problem constants
#define NB 2
#define SS 2048
#define HH 4096
#define NQH 32
#define NKVH 8
#define DH 128
#define MTOT (NB*SS)          // 4096 tokens
#define QC (NQH*DH)           // 4096
#define KVC (NKVH*DH)         // 1024
#define QKVN (QC + 2*KVC)     // 6144

typedef unsigned long long u64;
typedef unsigned int u32;

// ---------------- scratch (device globals; no allocation) ----------------
__device__ half g_hA[(size_t)MTOT*HH];        // hidden single fp16
__device__ half g_wqkvT[(size_t)QKVN*HH];     // w_qkv^T single fp16
__device__ half g_aA[(size_t)MTOT*QC];        // attn out single fp16
__device__ half g_woT[(size_t)HH*QC];         // w_o^T single fp16
__device__ half g_qh[(size_t)MTOT*QC];        // Q fp16 hi (scaled+RoPE)
__device__ half g_ql[(size_t)MTOT*QC];        // Q fp16 residual
__device__ half g_kh[(size_t)MTOT*KVC];       // K single fp16 (RoPE)
__device__ half g_vh[(size_t)MTOT*KVC];       // V single fp16

// ---------------- PTX helpers ----------------
__device__ __forceinline__ u32 smem_u32(const void* p){
    u32 a; asm("{ .reg .u64 t; cvta.to.shared.u64 t, %1; cvt.u32.u64 %0, t; }" : "=r"(a) : "l"(p));
    return a;
}
__device__ __forceinline__ void cpa16(u32 s, const void* g){
    asm volatile("cp.async.cg.shared.global [%0], [%1], 16;" :: "r"(s), "l"(g));
}
__device__ __forceinline__ void cp_commit(){ asm volatile("cp.async.commit_group;"); }
template<int N> __device__ __forceinline__ void cp_wait(){
    asm volatile("cp.async.wait_group %0;" :: "n"(N));
}
__device__ __forceinline__ void ldm_x4(u32 addr, u32& r0, u32& r1, u32& r2, u32& r3){
    asm volatile("ldmatrix.sync.aligned.m8n8.x4.shared.b16 {%0,%1,%2,%3}, [%4];"
                 : "=r"(r0), "=r"(r1), "=r"(r2), "=r"(r3) : "r"(addr));
}
__device__ __forceinline__ void ldm_x4t(u32 addr, u32& r0, u32& r1, u32& r2, u32& r3){
    asm volatile("ldmatrix.sync.aligned.m8n8.x4.trans.shared.b16 {%0,%1,%2,%3}, [%4];"
                 : "=r"(r0), "=r"(r1), "=r"(r2), "=r"(r3) : "r"(addr));
}
__device__ __forceinline__ void mma16816h(float* c, const u32* a, u32 b0, u32 b1){
    asm volatile("mma.sync.aligned.m16n8k16.row.col.f32.f16.f16.f32 "
                 "{%0,%1,%2,%3}, {%4,%5,%6,%7}, {%8,%9}, {%0,%1,%2,%3};"
                 : "+f"(c[0]), "+f"(c[1]), "+f"(c[2]), "+f"(c[3])
                 : "r"(a[0]), "r"(a[1]), "r"(a[2]), "r"(a[3]), "r"(b0), "r"(b1));
}
// split two fp32 into packed fp16 hi-pair + residual-pair
__device__ __forceinline__ void split2h(float x0, float x1, u32& hi, u32& lo){
    half h0 = __float2half_rn(x0), h1 = __float2half_rn(x1);
    hi = (u32)__half_as_ushort(h0) | ((u32)__half_as_ushort(h1) << 16);
    half l0 = __float2half_rn(x0 - __half2float(h0));
    half l1 = __float2half_rn(x1 - __half2float(h1));
    lo = (u32)__half_as_ushort(l0) | ((u32)__half_as_ushort(l1) << 16);
}
__device__ __forceinline__ u32 packh2(float x0, float x1){
    half2 h = __floats2half2_rn(x0, x1);
    return *(u32*)&h;
}

// =====================================================================
// Convert kernels
// =====================================================================
__global__ void conv_h4(const float4* __restrict__ src, ushort4* __restrict__ dst, int n4)
{
    int i = blockIdx.x * blockDim.x + threadIdx.x;
    if (i >= n4) return;
    float4 x = src[i];
    dst[i] = make_ushort4(__half_as_ushort(__float2half_rn(x.x)),
                          __half_as_ushort(__float2half_rn(x.y)),
                          __half_as_ushort(__float2half_rn(x.z)),
                          __half_as_ushort(__float2half_rn(x.w)));
}

// transpose + convert: src[R][C] fp32 -> dst[C][R] single fp16
__global__ void convT(const float* __restrict__ src, half* __restrict__ dstT,
                      int R, int Cc)
{
    __shared__ float t[64][33];
    int r0 = blockIdx.y * 64, c0 = blockIdx.x * 32;
    int tx = threadIdx.x, ty = threadIdx.y;  // (32,8)
    #pragma unroll
    for (int i = 0; i < 8; i++){
        int r = ty + i*8;
        t[r][tx] = src[(size_t)(r0 + r) * Cc + c0 + tx];
    }
    __syncthreads();
    #pragma unroll
    for (int i = 0; i < 4; i++){
        int cc = ty + i*8;
        half2 hv = __floats2half2_rn(t[tx*2][cc], t[tx*2+1][cc]);
        *(half2*)(dstT + (size_t)(c0 + cc) * R + r0 + tx*2) = hv;
    }
}

// =====================================================================
// HMMA fp16 GEMM: C[M,N] = A[M,K] * B[N,K]^T  (single-term fp16).
// 128x128 CTA tile, BK=64, 8 warps, 3-stage cp.async, single sync/iter.
// 2 CTAs/SM (216 KB smem). MODE 1: epilogue -> Q hi/lo + K,V fp16 + RoPE.
// MODE 0: C fp32.
// =====================================================================
#define GBK 64
#define ASTRB 144                      // 128 B row + 16 B pad
#define TILEB (128*ASTRB)              // 18432
#define STAGEB (2*TILEB)               // A, B = 36864
#define GSM (3*STAGEB)                 // 110592

template<int MODE>
__global__ __launch_bounds__(256, 2)
void mma_gemm(const half* __restrict__ Am, const half* __restrict__ Bm,
              float* __restrict__ C, const int* __restrict__ pos, int N, int K)
{
    extern __shared__ __align__(128) char sm[];
    const u32 sbuf = smem_u32(sm);
    const int tid = threadIdx.x, wid = tid >> 5, lid = tid & 31;
    const int wm = wid & 3, wn = wid >> 2;
    const int m0 = blockIdx.x * 128;
    const int n0 = blockIdx.y * 128;
    const int nk = K / GBK;

    float acc[2][8][4];
    #pragma unroll
    for (int t = 0; t < 2; t++)
        #pragma unroll
        for (int j = 0; j < 8; j++)
            #pragma unroll
            for (int q = 0; q < 4; q++) acc[t][j][q] = 0.f;

    // 128 rows x 8 chunks of 16B per tile; 1024 chunks, 4 per thread
    auto ldtile = [&](const half* g, int row0, int kc, u32 sb){
        #pragma unroll
        for (int i = 0; i < 4; i++){
            int c = tid + i*256;
            int r = c >> 3, kg = c & 7;
            cpa16(sb + r*ASTRB + kg*16, g + (size_t)(row0 + r)*K + kc + kg*8);
        }
    };
    auto ldstage = [&](int kc, int s){
        u32 sb = sbuf + s*STAGEB;
        ldtile(Am, m0, kc, sb);
        ldtile(Bm, n0, kc, sb + TILEB);
        cp_commit();
    };

    const u32 a_row = (u32)(wm*32 + (lid & 15));
    const u32 a_kb  = (u32)((lid >> 4) * 16);
    const u32 b_row = (u32)(wn*64 + ((lid >> 4) & 1)*8 + (lid & 7));
    const u32 b_kb  = (u32)(((lid >> 3) & 1) * 16);

    ldstage(0, 0);
    ldstage(GBK, 1);

    for (int kt = 0; kt < nk; kt++){
        if (kt + 1 < nk) cp_wait<1>(); else cp_wait<0>();
        __syncthreads();                       // stage kt visible; reads of kt-1 done
        if (kt + 2 < nk) ldstage((kt + 2)*GBK, (kt + 2) % 3);

        u32 ab = sbuf + (kt % 3)*STAGEB;
        #pragma unroll
        for (int k16 = 0; k16 < 4; k16++){
            u32 kb = (u32)(k16 * 32);
            u32 ah[2][4];
            #pragma unroll
            for (int t = 0; t < 2; t++){
                u32 ad = ab + (a_row + t*16)*ASTRB + kb + a_kb;
                ldm_x4(ad, ah[t][0], ah[t][1], ah[t][2], ah[t][3]);
            }
            #pragma unroll
            for (int p = 0; p < 4; p++){
                u32 bd = ab + TILEB + (b_row + p*16)*ASTRB + kb + b_kb;
                u32 h0, h1, h2, h3;
                ldm_x4(bd, h0, h1, h2, h3);
                #pragma unroll
                for (int t = 0; t < 2; t++){
                    mma16816h(acc[t][2*p],   ah[t], h0, h1);
                    mma16816h(acc[t][2*p+1], ah[t], h2, h3);
                }
            }
        }
    }

    // ---------------- epilogue ----------------
    const int mrow0 = m0 + wm*32 + (lid >> 2);
    const int colw = wn*64 + 2*(lid & 3);
    if (MODE == 0){
        #pragma unroll
        for (int t = 0; t < 2; t++)
            #pragma unroll
            for (int j = 0; j < 8; j++){
                int m = mrow0 + t*16;
                int nc = n0 + colw + j*8;
                *(float2*)&C[(size_t)m*N + nc]     = make_float2(acc[t][j][0], acc[t][j][1]);
                *(float2*)&C[(size_t)(m+8)*N + nc] = make_float2(acc[t][j][2], acc[t][j][3]);
            }
    } else {
        const int head = blockIdx.y;                    // BN == DH
        const float scale = 0.08838834764831845f;
        if (head < NQH){
            const int hd = head * DH;
            #pragma unroll
            for (int t = 0; t < 2; t++){
                int m = mrow0 + t*16;
                int p0 = pos[m], p1 = pos[m + 8];
                #pragma unroll
                for (int j = 0; j < 8; j++){
                    int d = colw + j*8;
                    float invf = exp2f((float)(d >> 1) * (-13.287712379549449f / 64.f));
                    float s0, c0s, s1, c1s;
                    sincosf((float)p0 * invf, &s0, &c0s);
                    sincosf((float)p1 * invf, &s1, &c1s);
                    float x1 = acc[t][j][0], x2 = acc[t][j][1];
                    float o1 = (x1*c0s - x2*s0)*scale, o2 = (x2*c0s + x1*s0)*scale;
                    float y1 = acc[t][j][2], y2 = acc[t][j][3];
                    float u1 = (y1*c1s - y2*s1)*scale, u2 = (y2*c1s + y1*s1)*scale;
                    u32 hi, lo;
                    split2h(o1, o2, hi, lo);
                    *(u32*)(g_qh + (size_t)m*QC + hd + d) = hi;
                    *(u32*)(g_ql + (size_t)m*QC + hd + d) = lo;
                    split2h(u1, u2, hi, lo);
                    *(u32*)(g_qh + (size_t)(m+8)*QC + hd + d) = hi;
                    *(u32*)(g_ql + (size_t)(m+8)*QC + hd + d) = lo;
                }
            }
        } else if (head < NQH + NKVH){
            const int hd = (head - NQH) * DH;
            #pragma unroll
            for (int t = 0; t < 2; t++){
                int m = mrow0 + t*16;
                int p0 = pos[m], p1 = pos[m + 8];
                #pragma unroll
                for (int j = 0; j < 8; j++){
                    int d = colw + j*8;
                    float invf = exp2f((float)(d >> 1) * (-13.287712379549449f / 64.f));
                    float s0, c0s, s1, c1s;
                    sincosf((float)p0 * invf, &s0, &c0s);
                    sincosf((float)p1 * invf, &s1, &c1s);
                    float x1 = acc[t][j][0], x2 = acc[t][j][1];
                    float y1 = acc[t][j][2], y2 = acc[t][j][3];
                    *(u32*)(g_kh + (size_t)m*KVC + hd + d) =
                        packh2(x1*c0s - x2*s0, x2*c0s + x1*s0);
                    *(u32*)(g_kh + (size_t)(m+8)*KVC + hd + d) =
                        packh2(y1*c1s - y2*s1, y2*c1s + y1*s1);
                }
            }
        } else {
            const int hd = (head - NQH - NKVH) * DH;
            #pragma unroll
            for (int t = 0; t < 2; t++)
                #pragma unroll
                for (int j = 0; j < 8; j++){
                    int m = mrow0 + t*16;
                    int d = colw + j*8;
                    *(u32*)(g_vh + (size_t)m*KVC + hd + d) =
                        packh2(acc[t][j][0], acc[t][j][1]);
                    *(u32*)(g_vh + (size_t)(m+8)*KVC + hd + d) =
                        packh2(acc[t][j][2], acc[t][j][3]);
                }
        }
    }
}

// =====================================================================
// Flash attention, fp16 HMMA: QK = (Qh+Ql)K (2 MMAs), PV = P*V (1 MMA).
// Q frags register-resident. KV double-buffered, single sync per tile.
// Long blocks first. Output written as single fp16 (O-proj is 1-term).
// =====================================================================
#define RSTR 272                       // 128 x 2B row + 16B pad
#define QREG (128*RSTR)                // 34816 per Q array
#define KVT  (64*RSTR)                 // 17408 per K/V array
#define KVSTAGE (2*KVT)                // kh, vh = 34816
#define ATTN_SMEM (2*QREG + 2*KVSTAGE) // 139264

__global__ __launch_bounds__(256, 1)
void attn_kernel()
{
    extern __shared__ __align__(128) char smA[];
    const u32 sb = smem_u32(smA);
    const int tid = threadIdx.x, wid = tid >> 5, lid = tid & 31;
    const int qt = gridDim.x - 1 - blockIdx.x;      // long blocks first
    const int h = blockIdx.y, b = blockIdx.z;
    const int hk = h >> 2;
    const int q0 = qt * 128;
    const int nt = qt*2 + 2;

    auto ldkv = [&](int k0, int s){
        #pragma unroll
        for (int i = 0; i < 8; i++){
            int idx = tid + i*256;
            int arr = idx >> 10, rem = idx & 1023;
            int r = rem >> 4, ch = rem & 15;
            const half* base = arr ? g_vh : g_kh;
            cpa16(sb + 2*QREG + s*KVSTAGE + arr*KVT + r*RSTR + ch*16,
                  base + (size_t)(b*SS + k0 + r)*KVC + hk*DH + ch*8);
        }
    };

    // prologue: Q (hi+lo) + KV0 in one group
    #pragma unroll
    for (int i = 0; i < 16; i++){
        int idx = tid + i*256;
        int arr = idx >> 11, rem = idx & 2047;
        int r = rem >> 4, ch = rem & 15;
        const half* src = (arr ? g_ql : g_qh)
            + (size_t)(b*SS + q0 + r)*QC + h*DH + ch*8;
        cpa16(sb + arr*QREG + r*RSTR + ch*16, src);
    }
    ldkv(0, 0);
    cp_commit();

    u32 qfh[8][4], qfl[8][4];
    float oacc[16][4];
    #pragma unroll
    for (int f = 0; f < 16; f++)
        #pragma unroll
        for (int q = 0; q < 4; q++) oacc[f][q] = 0.f;
    float mrow0 = -1e30f, mrow1 = -1e30f, lrow0 = 0.f, lrow1 = 0.f;

    const u32 a_base = (u32)((wid*16 + (lid & 15))*RSTR + (lid >> 4)*16);
    const u32 kb_row = (u32)((((lid >> 4) & 1)*8 + (lid & 7))*RSTR + ((lid >> 3) & 1)*16);
    const u32 vb_row = (u32)((((lid >> 3) & 1)*8 + (lid & 7))*RSTR + (lid >> 4)*16);

    for (int t = 0; t < nt; t++){
        cp_wait<0>();                  // stage t (and Q at t=0) complete
        __syncthreads();               // visible; reads of stage t-1 done
        if (t + 1 < nt){ ldkv((t + 1)*64, (t + 1) & 1); cp_commit(); }

        if (t == 0){
            #pragma unroll
            for (int ks = 0; ks < 8; ks++){
                u32 ad = sb + a_base + ks*32;
                ldm_x4(ad, qfh[ks][0], qfh[ks][1], qfh[ks][2], qfh[ks][3]);
                ldm_x4(ad + QREG, qfl[ks][0], qfl[ks][1], qfl[ks][2], qfl[ks][3]);
            }
        }

        const u32 kvb = sb + 2*QREG + (t & 1)*KVSTAGE;
        float s[8][4];
        #pragma unroll
        for (int f = 0; f < 8; f++)
            #pragma unroll
            for (int q = 0; q < 4; q++) s[f][q] = 0.f;

        // S = (Qh + Ql) K^T  (fp16 x2)
        #pragma unroll
        for (int ks = 0; ks < 8; ks++){
            #pragma unroll
            for (int p = 0; p < 4; p++){
                u32 ka = kvb + p*16*RSTR + kb_row + ks*32;
                u32 h0, h1, h2, h3;
                ldm_x4(ka, h0, h1, h2, h3);
                mma16816h(s[2*p],   qfh[ks], h0, h1);
                mma16816h(s[2*p],   qfl[ks], h0, h1);
                mma16816h(s[2*p+1], qfh[ks], h2, h3);
                mma16816h(s[2*p+1], qfl[ks], h2, h3);
            }
        }

        // causal mask (tiles near diagonal)
        if (t >= nt - 2){
            int k0 = t*64;
            int qg0 = q0 + wid*16 + (lid >> 2);
            #pragma unroll
            for (int f = 0; f < 8; f++){
                int kgb = k0 + f*8 + (lid & 3)*2;
                if (kgb     > qg0) s[f][0] = -1e30f;
                if (kgb + 1 > qg0) s[f][1] = -1e30f;
                if (kgb     > qg0 + 8) s[f][2] = -1e30f;
                if (kgb + 1 > qg0 + 8) s[f][3] = -1e30f;
            }
        }

        // online softmax
        float mx0 = -1e30f, mx1 = -1e30f;
        #pragma unroll
        for (int f = 0; f < 8; f++){
            mx0 = fmaxf(mx0, fmaxf(s[f][0], s[f][1]));
            mx1 = fmaxf(mx1, fmaxf(s[f][2], s[f][3]));
        }
        mx0 = fmaxf(mx0, __shfl_xor_sync(0xffffffffu, mx0, 1));
        mx0 = fmaxf(mx0, __shfl_xor_sync(0xffffffffu, mx0, 2));
        mx1 = fmaxf(mx1, __shfl_xor_sync(0xffffffffu, mx1, 1));
        mx1 = fmaxf(mx1, __shfl_xor_sync(0xffffffffu, mx1, 2));
        float mn0 = fmaxf(mrow0, mx0), mn1 = fmaxf(mrow1, mx1);
        float al0 = __expf(mrow0 - mn0), al1 = __expf(mrow1 - mn1);
        mrow0 = mn0; mrow1 = mn1;
        float rs0 = 0.f, rs1 = 0.f;
        #pragma unroll
        for (int f = 0; f < 8; f++){
            s[f][0] = __expf(s[f][0] - mn0); rs0 += s[f][0];
            s[f][1] = __expf(s[f][1] - mn0); rs0 += s[f][1];
            s[f][2] = __expf(s[f][2] - mn1); rs1 += s[f][2];
            s[f][3] = __expf(s[f][3] - mn1); rs1 += s[f][3];
        }
        rs0 += __shfl_xor_sync(0xffffffffu, rs0, 1);
        rs0 += __shfl_xor_sync(0xffffffffu, rs0, 2);
        rs1 += __shfl_xor_sync(0xffffffffu, rs1, 1);
        rs1 += __shfl_xor_sync(0xffffffffu, rs1, 2);
        lrow0 = lrow0*al0 + rs0;
        lrow1 = lrow1*al1 + rs1;
        #pragma unroll
        for (int f = 0; f < 16; f++){
            oacc[f][0] *= al0; oacc[f][1] *= al0;
            oacc[f][2] *= al1; oacc[f][3] *= al1;
        }

        // O += P V  (P single fp16, V single fp16)
        #pragma unroll
        for (int kk = 0; kk < 4; kk++){
            u32 ph[4];
            ph[0] = packh2(s[2*kk][0],   s[2*kk][1]);
            ph[1] = packh2(s[2*kk][2],   s[2*kk][3]);
            ph[2] = packh2(s[2*kk+1][0], s[2*kk+1][1]);
            ph[3] = packh2(s[2*kk+1][2], s[2*kk+1][3]);
            #pragma unroll
            for (int p = 0; p < 8; p++){
                u32 va = kvb + KVT + kk*16*RSTR + vb_row + p*32;
                u32 h0, h1, h2, h3;
                ldm_x4t(va, h0, h1, h2, h3);
                mma16816h(oacc[2*p],   ph, h0, h1);
                mma16816h(oacc[2*p+1], ph, h2, h3);
            }
        }
    }

    // epilogue: divide by l, write single fp16 (O-proj A operand)
    float inv0 = 1.f / lrow0, inv1 = 1.f / lrow1;
    const int row0 = q0 + wid*16 + (lid >> 2);
    const size_t tok0 = (size_t)(b*SS + row0);
    #pragma unroll
    for (int f = 0; f < 16; f++){
        int col = h*DH + f*8 + (lid & 3)*2;
        *(u32*)(g_aA + tok0*QC + col)     = packh2(oacc[f][0]*inv0, oacc[f][1]*inv0);
        *(u32*)(g_aA + (tok0+8)*QC + col) = packh2(oacc[f][2]*inv1, oacc[f][3]*inv1);
    }
}

// =====================================================================
extern "C" void kernel_launch(void* const* d_in, const int* in_sizes, int n_in,
                              void* d_out, int out_size)
{
    const float* hidden = (const float*)d_in[0];
    const float* wqkv   = (const float*)d_in[1];
    const float* wo     = (const float*)d_in[2];
    const int*   pos    = (const int*)d_in[3];
    float* out = (float*)d_out;

    void *p_hA, *p_wqkvT, *p_aA, *p_woT;
    cudaGetSymbolAddress(&p_hA, g_hA);
    cudaGetSymbolAddress(&p_wqkvT, g_wqkvT);
    cudaGetSymbolAddress(&p_aA, g_aA);
    cudaGetSymbolAddress(&p_woT, g_woT);

    cudaFuncSetAttribute(mma_gemm<1>, cudaFuncAttributeMaxDynamicSharedMemorySize, GSM);
    cudaFuncSetAttribute(mma_gemm<0>, cudaFuncAttributeMaxDynamicSharedMemorySize, GSM);
    cudaFuncSetAttribute(attn_kernel, cudaFuncAttributeMaxDynamicSharedMemorySize, ATTN_SMEM);

    // 1) convert hidden to single fp16
    {
        int n4 = (int)((size_t)MTOT * HH / 4);
        conv_h4<<<(n4 + 255)/256, 256>>>((const float4*)hidden, (ushort4*)p_hA, n4);
    }
    // 2) transpose+convert weights -> [N][K] single fp16
    convT<<<dim3(QKVN/32, HH/64), dim3(32, 8)>>>(wqkv, (half*)p_wqkvT, HH, QKVN);
    convT<<<dim3(HH/32, QC/64), dim3(32, 8)>>>(wo, (half*)p_woT, QC, HH);

    // 3) QKV projection (fp16, 1-term) + fused RoPE + split epilogue
    mma_gemm<1><<<dim3(MTOT/128, QKVN/128), 256, GSM>>>(
        (const half*)p_hA, (const half*)p_wqkvT, nullptr, pos, QKVN, HH);

    // 4) causal GQA flash attention -> writes aA single fp16
    attn_kernel<<<dim3(SS/128, NQH, NB), 256, ATTN_SMEM>>>();

    // 5) output projection (fp16, 1-term)
    mma_gemm<0><<<dim3(MTOT/128, HH/128), 256, GSM>>>(
        (const half*)p_aA, (const half*)p_woT, out, nullptr, HH, QC);
}